// round 1
// baseline (speedup 1.0000x reference)
#include <cuda_runtime.h>
#include <math.h>

#define D_ 1024
#define L_ 2048
#define B_ 2

// ---------------- scratch (device globals; no allocs allowed) ----------------
__device__ float g_x [B_ * L_ * D_];          // activations
__device__ float g_t1[B_ * L_ * D_];          // dwconv out / attention out
__device__ float g_t2[B_ * L_ * 2 * D_];      // pointwise out / kv
__device__ float g_q [B_ * L_ * D_];          // q / attn projection
__device__ float g_kp[B_ * 2 * L_ * 512];     // K packed: [b][G][L][512]
__device__ float g_vt[B_ * 512 * 2 * L_];     // V packed transposed: [b][512][G*2048+L]
__device__ float g_s [4LL * L_ * 4096];       // scores: [bg][l][G*2048+L]
__device__ float g_rs[4 * L_ * 2 * 2];        // row stats (max, 1/sum): [bg][l][G]{m,inv}

struct Batch8 {
    long long offA[8];
    long long offB[8];
    long long offC[8];
    long long offS[8];
    float alpha[8];
};

// ---------------- Julia embedding ----------------
__global__ __launch_bounds__(256) void k_embed(
    const int* __restrict__ tok, const float* __restrict__ ctab,
    const float* __restrict__ projw, const float* __restrict__ escale,
    float* __restrict__ x)
{
    int bl = blockIdx.x;
    int t = tok[bl];
    float cr = ctab[2 * t], ci = ctab[2 * t + 1];
    float f[16];
    float zr = 0.f, zi = 0.f;
#pragma unroll
    for (int s = 0; s < 8; s++) {
        float nr = zr * zr - zi * zi + cr;
        float ni = 2.f * zr * zi + ci;
        zr = nr; zi = ni;
        f[2 * s] = zr; f[2 * s + 1] = zi;
    }
    float es = escale[0];
    int d0 = threadIdx.x * 4;
    float4 o;
    float* op = &o.x;
#pragma unroll
    for (int j = 0; j < 4; j++) {
        const float* w = projw + (size_t)(d0 + j) * 16;
        float acc = 0.f;
#pragma unroll
        for (int k = 0; k < 16; k++) acc = fmaf(f[k], w[k], acc);
        op[j] = acc * es;
    }
    *(float4*)(x + (size_t)bl * D_ + d0) = o;
}

// ---------------- depthwise conv (K=5, zero pad) ----------------
__global__ __launch_bounds__(256) void k_dwconv(
    const float* __restrict__ x, const float* __restrict__ w,
    const float* __restrict__ bias, float* __restrict__ y)
{
    int idx = blockIdx.x * blockDim.x + threadIdx.x;
    int d = idx & (D_ - 1);
    int l = (idx >> 10) & (L_ - 1);
    int b = idx >> 21;
    float acc = bias[d];
#pragma unroll
    for (int k = 0; k < 5; k++) {
        int ll = l + k - 2;
        if (ll >= 0 && ll < L_)
            acc = fmaf(x[((size_t)b * L_ + ll) * D_ + d], w[d * 5 + k], acc);
    }
    y[idx] = acc;
}

// ---------------- tiled SGEMM: C = alpha * A(MxK) * B(NxK)^T (+bias per col) ----------------
// Optional fused softmax on A: A'[r][k] = exp(A-m[r,G])*inv[r,G], G = k>>11.
__global__ __launch_bounds__(256) void sgemm_nt(
    const float* __restrict__ Ab, const float* __restrict__ Bb,
    float* __restrict__ Cb, const float* __restrict__ bias,
    const float* __restrict__ rsb,
    int K, int lda, int ldb, int ldc, Batch8 bt)
{
    const int z = blockIdx.z;
    const float* A = Ab + bt.offA[z];
    const float* B = Bb + bt.offB[z];
    float* C = Cb + bt.offC[z];
    const float alpha = bt.alpha[z];

    __shared__ float As[16][128];
    __shared__ float Bs[16][128];

    const int tid = threadIdx.x;
    const int bm = blockIdx.y * 128;
    const int bn = blockIdx.x * 128;

    const int lr = tid >> 2;          // 0..63
    const int lk = (tid & 3) << 2;    // 0,4,8,12
    const int ty = tid >> 4;          // 0..15
    const int tx = tid & 15;          // 0..15

    float acc[8][8];
#pragma unroll
    for (int i = 0; i < 8; i++)
#pragma unroll
        for (int j = 0; j < 8; j++) acc[i][j] = 0.f;

    const float2* rs2 = rsb ? (const float2*)(rsb + bt.offS[z]) : nullptr;

    for (int k0 = 0; k0 < K; k0 += 16) {
        const int Gk = k0 >> 11;
#pragma unroll
        for (int i = 0; i < 2; i++) {
            int r = lr + i * 64;
            float4 a = *(const float4*)(A + (size_t)(bm + r) * lda + k0 + lk);
            if (rs2) {
                float2 st = rs2[(size_t)(bm + r) * 2 + Gk];
                a.x = __expf(a.x - st.x) * st.y;
                a.y = __expf(a.y - st.x) * st.y;
                a.z = __expf(a.z - st.x) * st.y;
                a.w = __expf(a.w - st.x) * st.y;
            }
            As[lk + 0][r] = a.x; As[lk + 1][r] = a.y;
            As[lk + 2][r] = a.z; As[lk + 3][r] = a.w;
        }
#pragma unroll
        for (int i = 0; i < 2; i++) {
            int r = lr + i * 64;
            float4 b4 = *(const float4*)(B + (size_t)(bn + r) * ldb + k0 + lk);
            Bs[lk + 0][r] = b4.x; Bs[lk + 1][r] = b4.y;
            Bs[lk + 2][r] = b4.z; Bs[lk + 3][r] = b4.w;
        }
        __syncthreads();
#pragma unroll
        for (int kk = 0; kk < 16; kk++) {
            float a[8], b[8];
            *(float4*)(a)     = *(const float4*)(&As[kk][ty * 8]);
            *(float4*)(a + 4) = *(const float4*)(&As[kk][ty * 8 + 4]);
            *(float4*)(b)     = *(const float4*)(&Bs[kk][tx * 8]);
            *(float4*)(b + 4) = *(const float4*)(&Bs[kk][tx * 8 + 4]);
#pragma unroll
            for (int i = 0; i < 8; i++)
#pragma unroll
                for (int j = 0; j < 8; j++)
                    acc[i][j] = fmaf(a[i], b[j], acc[i][j]);
        }
        __syncthreads();
    }

#pragma unroll
    for (int i = 0; i < 8; i++) {
        size_t row = (size_t)bm + ty * 8 + i;
#pragma unroll
        for (int j = 0; j < 8; j += 4) {
            int col = bn + tx * 8 + j;
            float4 o;
            o.x = acc[i][j + 0] * alpha;
            o.y = acc[i][j + 1] * alpha;
            o.z = acc[i][j + 2] * alpha;
            o.w = acc[i][j + 3] * alpha;
            if (bias) {
                float4 bv = *(const float4*)(bias + col);
                o.x += bv.x; o.y += bv.y; o.z += bv.z; o.w += bv.w;
            }
            *(float4*)(C + row * ldc + col) = o;
        }
    }
}

// ---------------- GLU + residual + LayerNorm ----------------
__global__ __launch_bounds__(256) void k_glu_ln(
    const float* __restrict__ x, const float* __restrict__ y2,
    const float* __restrict__ gbias, const float* __restrict__ lng,
    const float* __restrict__ lnb, float* __restrict__ out)
{
    int bl = blockIdx.x;
    int tid = threadIdx.x;
    int c = tid * 4;
    const float* xr = x + (size_t)bl * D_;
    const float* yr = y2 + (size_t)bl * 2 * D_;
    float4 xv = *(const float4*)(xr + c);
    float4 sv = *(const float4*)(yr + c);
    float4 gv = *(const float4*)(yr + D_ + c);
    float4 gb = *(const float4*)(gbias + c);
    float t0 = xv.x + sv.x * (1.f / (1.f + __expf(-(gv.x + gb.x))));
    float t1 = xv.y + sv.y * (1.f / (1.f + __expf(-(gv.y + gb.y))));
    float t2 = xv.z + sv.z * (1.f / (1.f + __expf(-(gv.z + gb.z))));
    float t3 = xv.w + sv.w * (1.f / (1.f + __expf(-(gv.w + gb.w))));

    __shared__ float red[256];
    red[tid] = t0 + t1 + t2 + t3;
    __syncthreads();
    for (int o = 128; o > 0; o >>= 1) { if (tid < o) red[tid] += red[tid + o]; __syncthreads(); }
    float m = red[0] * (1.f / 1024.f);
    __syncthreads();
    float d0 = t0 - m, d1 = t1 - m, d2 = t2 - m, d3 = t3 - m;
    red[tid] = d0 * d0 + d1 * d1 + d2 * d2 + d3 * d3;
    __syncthreads();
    for (int o = 128; o > 0; o >>= 1) { if (tid < o) red[tid] += red[tid + o]; __syncthreads(); }
    float inv = rsqrtf(red[0] * (1.f / 1024.f) + 1e-5f);
    float4 gg = *(const float4*)(lng + c);
    float4 bb = *(const float4*)(lnb + c);
    float4 o4;
    o4.x = d0 * inv * gg.x + bb.x;
    o4.y = d1 * inv * gg.y + bb.y;
    o4.z = d2 * inv * gg.z + bb.z;
    o4.w = d3 * inv * gg.w + bb.w;
    *(float4*)(out + (size_t)bl * D_ + c) = o4;
}

// ---------------- residual add + LayerNorm ----------------
__global__ __launch_bounds__(256) void k_add_ln(
    const float* __restrict__ x, const float* __restrict__ zv,
    const float* __restrict__ lng, const float* __restrict__ lnb,
    float* __restrict__ out)
{
    int bl = blockIdx.x;
    int tid = threadIdx.x;
    int c = tid * 4;
    float4 xv = *(const float4*)(x + (size_t)bl * D_ + c);
    float4 zz = *(const float4*)(zv + (size_t)bl * D_ + c);
    float t0 = xv.x + zz.x, t1 = xv.y + zz.y, t2 = xv.z + zz.z, t3 = xv.w + zz.w;

    __shared__ float red[256];
    red[tid] = t0 + t1 + t2 + t3;
    __syncthreads();
    for (int o = 128; o > 0; o >>= 1) { if (tid < o) red[tid] += red[tid + o]; __syncthreads(); }
    float m = red[0] * (1.f / 1024.f);
    __syncthreads();
    float d0 = t0 - m, d1 = t1 - m, d2 = t2 - m, d3 = t3 - m;
    red[tid] = d0 * d0 + d1 * d1 + d2 * d2 + d3 * d3;
    __syncthreads();
    for (int o = 128; o > 0; o >>= 1) { if (tid < o) red[tid] += red[tid + o]; __syncthreads(); }
    float inv = rsqrtf(red[0] * (1.f / 1024.f) + 1e-5f);
    float4 gg = *(const float4*)(lng + c);
    float4 bb = *(const float4*)(lnb + c);
    float4 o4;
    o4.x = d0 * inv * gg.x + bb.x;
    o4.y = d1 * inv * gg.y + bb.y;
    o4.z = d2 * inv * gg.z + bb.z;
    o4.w = d3 * inv * gg.w + bb.w;
    *(float4*)(out + (size_t)bl * D_ + c) = o4;
}

// ---------------- repack kv -> Kp [b][G][L][512], Vt [b][512][G*2048+L] ----------------
__global__ __launch_bounds__(256) void k_pack(
    const float* __restrict__ kv, float* __restrict__ kp, float* __restrict__ vt)
{
    int idx = blockIdx.x * blockDim.x + threadIdx.x;   // b,l,head(16),d(64)
    int d = idx & 63;
    int h16 = (idx >> 6) & 15;
    int l = (idx >> 10) & (L_ - 1);
    int b = idx >> 21;
    int G = h16 >> 3, h = h16 & 7;
    const float* base = kv + ((size_t)b * L_ + l) * 2048 + h16 * 128 + d;
    float kvk = base[0];
    float kvv = base[64];
    kp[(((size_t)(b * 2 + G) * L_ + l) * 512) + h * 64 + d] = kvk;
    vt[((size_t)b * 512 + h * 64 + d) * 4096 + G * 2048 + l] = kvv;
}

// ---------------- per-row softmax stats: (max, 1/sum(exp)) ----------------
__global__ __launch_bounds__(256) void k_rowstats(
    const float* __restrict__ S, float* __restrict__ rs)
{
    int l = blockIdx.x, G = blockIdx.y, bg = blockIdx.z;
    const float* row = S + ((size_t)bg * L_ + l) * 4096 + G * 2048;
    int tid = threadIdx.x;
    float v[8];
    float m = -INFINITY;
#pragma unroll
    for (int j = 0; j < 8; j++) { v[j] = row[tid + j * 256]; m = fmaxf(m, v[j]); }
    __shared__ float red[256];
    red[tid] = m;
    __syncthreads();
    for (int o = 128; o > 0; o >>= 1) { if (tid < o) red[tid] = fmaxf(red[tid], red[tid + o]); __syncthreads(); }
    m = red[0];
    __syncthreads();
    float s = 0.f;
#pragma unroll
    for (int j = 0; j < 8; j++) s += __expf(v[j] - m);
    red[tid] = s;
    __syncthreads();
    for (int o = 128; o > 0; o >>= 1) { if (tid < o) red[tid] += red[tid + o]; __syncthreads(); }
    if (tid == 0) {
        float* p = rs + ((size_t)(bg * L_ + l) * 2 + G) * 2;
        p[0] = m;
        p[1] = 1.f / red[0];
    }
}

// ---------------- host ----------------
static void fill1(Batch8& bt)
{
    for (int z = 0; z < 8; z++) {
        bt.offA[z] = bt.offB[z] = bt.offC[z] = bt.offS[z] = 0;
        bt.alpha[z] = 1.f;
    }
}

extern "C" void kernel_launch(void* const* d_in, const int* in_sizes, int n_in,
                              void* d_out, int out_size)
{
    (void)in_sizes; (void)n_in; (void)out_size;
    const int*   tok    = (const int*)  d_in[0];
    const float* ctab   = (const float*)d_in[1];
    const float* projw  = (const float*)d_in[2];
    const float* escale = (const float*)d_in[3];
    const float* dww    = (const float*)d_in[4];
    const float* dwb    = (const float*)d_in[5];
    const float* pww    = (const float*)d_in[6];
    const float* pwb    = (const float*)d_in[7];
    const float* gbias  = (const float*)d_in[8];
    const float* clng   = (const float*)d_in[9];
    const float* clnb   = (const float*)d_in[10];
    const float* qw     = (const float*)d_in[11];
    const float* kvw    = (const float*)d_in[12];
    const float* ow     = (const float*)d_in[13];
    const float* alng   = (const float*)d_in[14];
    const float* alnb   = (const float*)d_in[15];

    float *x, *t1, *t2, *q, *kp, *vt, *S, *rs;
    cudaGetSymbolAddress((void**)&x,  g_x);
    cudaGetSymbolAddress((void**)&t1, g_t1);
    cudaGetSymbolAddress((void**)&t2, g_t2);
    cudaGetSymbolAddress((void**)&q,  g_q);
    cudaGetSymbolAddress((void**)&kp, g_kp);
    cudaGetSymbolAddress((void**)&vt, g_vt);
    cudaGetSymbolAddress((void**)&S,  g_s);
    cudaGetSymbolAddress((void**)&rs, g_rs);

    k_embed<<<B_ * L_, 256>>>(tok, ctab, projw, escale, x);

    for (int i = 0; i < 2; i++) {
        // --- conv block ---
        k_dwconv<<<(B_ * L_ * D_) / 256, 256>>>(x, dww + (size_t)i * D_ * 5, dwb + i * D_, t1);

        Batch8 b1; fill1(b1);
        // pointwise: (4096 x 2048) = t1(4096x1024) * pw_w(2048x1024)^T + pw_b
        sgemm_nt<<<dim3(16, 32, 1), 256>>>(t1, pww + (size_t)i * 2048 * 1024, t2,
                                           pwb + i * 2048, nullptr,
                                           1024, 1024, 1024, 2048, b1);

        k_glu_ln<<<B_ * L_, 256>>>(x, t2, gbias + i * D_, clng + i * D_, clnb + i * D_, x);

        // --- attention block ---
        sgemm_nt<<<dim3(8, 32, 1), 256>>>(x, qw + (size_t)i * D_ * D_, q,
                                          nullptr, nullptr, 1024, 1024, 1024, 1024, b1);
        sgemm_nt<<<dim3(16, 32, 1), 256>>>(x, kvw + (size_t)i * 2048 * 1024, t2,
                                           nullptr, nullptr, 1024, 1024, 1024, 2048, b1);

        k_pack<<<(B_ * L_ * 16 * 64) / 256, 256>>>(t2, kp, vt);

        // scores: per (b,g,G): Q_bg(2048x512) * Kp_bG(2048x512)^T * SCALE * fs[G]
        Batch8 bs; fill1(bs);
        for (int zz = 0; zz < 8; zz++) {
            int bg = zz >> 1, G = zz & 1;
            int b = bg >> 1, g = bg & 1;
            bs.offA[zz] = (long long)b * L_ * 1024 + g * 512;
            bs.offB[zz] = (long long)(b * 2 + G) * L_ * 512;
            bs.offC[zz] = (long long)bg * L_ * 4096 + G * 2048;
            bs.alpha[zz] = 0.125f * (G ? 2.0f : 1.0f);
        }
        sgemm_nt<<<dim3(16, 16, 8), 256>>>(q, kp, S, nullptr, nullptr,
                                           512, 1024, 512, 4096, bs);

        k_rowstats<<<dim3(L_, 2, 4), 256>>>(S, rs);

        // attention out: O(2048x512) = softmax(S)(2048x4096) * Vt(512x4096)^T
        Batch8 bo; fill1(bo);
        for (int zz = 0; zz < 4; zz++) {
            int b = zz >> 1, g = zz & 1;
            bo.offA[zz] = (long long)zz * L_ * 4096;
            bo.offB[zz] = (long long)b * 512 * 4096;
            bo.offC[zz] = (long long)b * L_ * 1024 + g * 512;
            bo.offS[zz] = (long long)zz * L_ * 4;
        }
        sgemm_nt<<<dim3(4, 16, 4), 256>>>(S, vt, t1, nullptr, rs,
                                          4096, 4096, 4096, 1024, bo);

        // out projection
        sgemm_nt<<<dim3(8, 32, 1), 256>>>(t1, ow + (size_t)i * D_ * D_, q,
                                          nullptr, nullptr, 1024, 1024, 1024, 1024, b1);

        float* dst = (i == 1) ? (float*)d_out : x;
        k_add_ln<<<B_ * L_, 256>>>(x, q, alng + i * D_, alnb + i * D_, dst);
    }
}

// round 3
// speedup vs baseline: 2.5839x; 2.5839x over previous
#include <cuda_runtime.h>
#include <cuda_bf16.h>
#include <math.h>
#include <stdint.h>

#define D_ 1024
#define L_ 2048
#define B_ 2

// GEMM tile config: CTA 128x256, 512 threads, warp grid 4M x 4N, warp tile 32x64
#define KC 16
#define STAGE_U32 9216          // Ah 1536 | Al 1536 | Bh 3072 | Bl 3072 (u32 words)
#define GEMM_SMEM (2 * STAGE_U32 * 4)

// ---------------- scratch (device globals; no allocs allowed) ----------------
__device__ float g_x [B_ * L_ * D_];
__device__ float g_t1[B_ * L_ * D_];
__device__ float g_t2[B_ * L_ * 2 * D_];
__device__ float g_q [B_ * L_ * D_];
__device__ float g_kp[B_ * 2 * L_ * 512];     // K packed: [b][G][L][512]
__device__ float g_vt[B_ * 512 * 2 * L_];     // V packed transposed: [b][512][G*2048+L]
__device__ float g_s [4LL * L_ * 4096];       // scores: [bg][l][G*2048+L]
__device__ float g_rs[4 * L_ * 2 * 2];        // row stats (max, 1/sum)

struct Batch8 {
    long long offA[8];
    long long offB[8];
    long long offC[8];
    long long offS[8];
    float alpha[8];
};

// split fp32 pair into packed bf16 hi + bf16 lo (lo = x - hi); low half = first arg
__device__ __forceinline__ void split2(float a, float b, uint32_t& hi, uint32_t& lo) {
    uint32_t h;
    asm("cvt.rn.satfinite.bf16x2.f32 %0, %1, %2;" : "=r"(h) : "f"(b), "f"(a));
    float ra = a - __uint_as_float(h << 16);
    float rb = b - __uint_as_float(h & 0xffff0000u);
    uint32_t l;
    asm("cvt.rn.satfinite.bf16x2.f32 %0, %1, %2;" : "=r"(l) : "f"(rb), "f"(ra));
    hi = h; lo = l;
}

__device__ __forceinline__ void mma_bf16(float* c, const uint32_t* a, uint32_t b0, uint32_t b1) {
    asm volatile(
        "mma.sync.aligned.m16n8k16.row.col.f32.bf16.bf16.f32 "
        "{%0,%1,%2,%3}, {%4,%5,%6,%7}, {%8,%9}, {%0,%1,%2,%3};"
        : "+f"(c[0]), "+f"(c[1]), "+f"(c[2]), "+f"(c[3])
        : "r"(a[0]), "r"(a[1]), "r"(a[2]), "r"(a[3]), "r"(b0), "r"(b1));
}

// ---------------- split-bf16 mma.sync GEMM: C = alpha * A(MxK) * B(NxK)^T (+bias) ----------------
// Optional fused softmax on A: A'[r][k] = exp(A-m[r,G])*inv[r,G], G = k>>11.
__global__ __launch_bounds__(512, 1) void gemm_mma(
    const float* __restrict__ Ab, const float* __restrict__ Bb,
    float* __restrict__ Cb, const float* __restrict__ bias,
    const float* __restrict__ rsb,
    int K, int lda, int ldb, int ldc, Batch8 bt)
{
    extern __shared__ uint32_t smw[];

    const int z = blockIdx.z;
    const float* A = Ab + bt.offA[z];
    const float* B = Bb + bt.offB[z];
    float* C = Cb + bt.offC[z];
    const float alpha = bt.alpha[z];
    const float2* rs2 = rsb ? (const float2*)(rsb + bt.offS[z]) : nullptr;

    const int tid = threadIdx.x;
    const int bm = blockIdx.y * 128;
    const int bn = blockIdx.x * 256;

    const int lane = tid & 31;
    const int wid = tid >> 5;
    const int wm = wid >> 2;        // 0..3  (M warp)
    const int wn = wid & 3;         // 0..3  (N warp)
    const int qr = lane >> 2;       // 0..7
    const int qc = lane & 3;        // 0..3

    // staging: thread handles A row (tid>>2), B rows (tid>>2) and (tid>>2)+128, k-quad (tid&3)
    const int ar = tid >> 2;
    const int aw = tid & 3;
    const float* aptr  = A + (size_t)(bm + ar) * lda + aw * 4;
    const float* bptr0 = B + (size_t)(bn + ar) * ldb + aw * 4;
    const float* bptr1 = B + (size_t)(bn + ar + 128) * ldb + aw * 4;

    float acc[2][8][4];
#pragma unroll
    for (int i = 0; i < 2; i++)
#pragma unroll
        for (int j = 0; j < 8; j++)
#pragma unroll
            for (int c = 0; c < 4; c++) acc[i][j][c] = 0.f;

    const int nk = K >> 4;

    float4 av, bv0, bv1;
    av  = *(const float4*)aptr;
    bv0 = *(const float4*)bptr0;
    bv1 = *(const float4*)bptr1;

    auto store_stage = [&](int st, int k0) {
        const int so = st * STAGE_U32;
        float4 a = av;
        if (rs2) {
            float2 s = rs2[(size_t)(bm + ar) * 2 + (k0 >> 11)];
            a.x = __expf(a.x - s.x) * s.y;
            a.y = __expf(a.y - s.x) * s.y;
            a.z = __expf(a.z - s.x) * s.y;
            a.w = __expf(a.w - s.x) * s.y;
        }
        uint32_t h0, l0, h1, l1;
        split2(a.x, a.y, h0, l0); split2(a.z, a.w, h1, l1);
        uint32_t* pA = &smw[so + ar * 12 + aw * 2];
        pA[0] = h0; pA[1] = h1;
        pA[1536] = l0; pA[1537] = l1;
        split2(bv0.x, bv0.y, h0, l0); split2(bv0.z, bv0.w, h1, l1);
        uint32_t* pB = &smw[so + 3072 + ar * 12 + aw * 2];
        pB[0] = h0; pB[1] = h1;
        pB[3072] = l0; pB[3073] = l1;
        split2(bv1.x, bv1.y, h0, l0); split2(bv1.z, bv1.w, h1, l1);
        uint32_t* pB2 = &smw[so + 3072 + (ar + 128) * 12 + aw * 2];
        pB2[0] = h0; pB2[1] = h1;
        pB2[3072] = l0; pB2[3073] = l1;
    };

    store_stage(0, 0);
    __syncthreads();

    for (int kt = 0; kt < nk; kt++) {
        const int k0n = (kt + 1) << 4;
        if (kt + 1 < nk) {
            av  = *(const float4*)(aptr + k0n);
            bv0 = *(const float4*)(bptr0 + k0n);
            bv1 = *(const float4*)(bptr1 + k0n);
        }
        // ---- compute on stage kt&1 ----
        {
            const int so = (kt & 1) * STAGE_U32;
            uint32_t ah[2][4], al[2][4];
#pragma unroll
            for (int mb = 0; mb < 2; mb++) {
                const int r0 = wm * 32 + mb * 16 + qr;
                const uint32_t* pa = &smw[so + r0 * 12];
                ah[mb][0] = pa[qc];           ah[mb][1] = pa[8 * 12 + qc];
                ah[mb][2] = pa[qc + 4];       ah[mb][3] = pa[8 * 12 + qc + 4];
                al[mb][0] = pa[1536 + qc];    al[mb][1] = pa[1536 + 8 * 12 + qc];
                al[mb][2] = pa[1536 + qc + 4];al[mb][3] = pa[1536 + 8 * 12 + qc + 4];
            }
#pragma unroll
            for (int nb = 0; nb < 8; nb++) {
                const int rn = wn * 64 + nb * 8 + qr;
                const uint32_t* pb = &smw[so + 3072 + rn * 12];
                const uint32_t bh0 = pb[qc], bh1 = pb[qc + 4];
                const uint32_t bl0 = pb[3072 + qc], bl1 = pb[3072 + qc + 4];
#pragma unroll
                for (int mb = 0; mb < 2; mb++) {
                    mma_bf16(acc[mb][nb], ah[mb], bh0, bh1);
                    mma_bf16(acc[mb][nb], ah[mb], bl0, bl1);
                    mma_bf16(acc[mb][nb], al[mb], bh0, bh1);
                }
            }
        }
        if (kt + 1 < nk) store_stage((kt + 1) & 1, k0n);
        __syncthreads();
    }

    // ---- epilogue ----
#pragma unroll
    for (int mb = 0; mb < 2; mb++) {
        const int row = bm + wm * 32 + mb * 16 + qr;
#pragma unroll
        for (int nb = 0; nb < 8; nb++) {
            const int col = bn + wn * 64 + nb * 8 + qc * 2;
            float2 v0, v1;
            v0.x = acc[mb][nb][0] * alpha;
            v0.y = acc[mb][nb][1] * alpha;
            v1.x = acc[mb][nb][2] * alpha;
            v1.y = acc[mb][nb][3] * alpha;
            if (bias) {
                float2 bv = *(const float2*)(bias + col);
                v0.x += bv.x; v0.y += bv.y;
                v1.x += bv.x; v1.y += bv.y;
            }
            *(float2*)(C + (size_t)row * ldc + col) = v0;
            *(float2*)(C + (size_t)(row + 8) * ldc + col) = v1;
        }
    }
}

// ---------------- Julia embedding ----------------
__global__ __launch_bounds__(256) void k_embed(
    const int* __restrict__ tok, const float* __restrict__ ctab,
    const float* __restrict__ projw, const float* __restrict__ escale,
    float* __restrict__ x)
{
    int bl = blockIdx.x;
    int t = tok[bl];
    float cr = ctab[2 * t], ci = ctab[2 * t + 1];
    float f[16];
    float zr = 0.f, zi = 0.f;
#pragma unroll
    for (int s = 0; s < 8; s++) {
        float nr = zr * zr - zi * zi + cr;
        float ni = 2.f * zr * zi + ci;
        zr = nr; zi = ni;
        f[2 * s] = zr; f[2 * s + 1] = zi;
    }
    float es = escale[0];
    int d0 = threadIdx.x * 4;
    float4 o;
    float* op = &o.x;
#pragma unroll
    for (int j = 0; j < 4; j++) {
        const float* w = projw + (size_t)(d0 + j) * 16;
        float acc = 0.f;
#pragma unroll
        for (int k = 0; k < 16; k++) acc = fmaf(f[k], w[k], acc);
        op[j] = acc * es;
    }
    *(float4*)(x + (size_t)bl * D_ + d0) = o;
}

// ---------------- depthwise conv (K=5, zero pad) ----------------
__global__ __launch_bounds__(256) void k_dwconv(
    const float* __restrict__ x, const float* __restrict__ w,
    const float* __restrict__ bias, float* __restrict__ y)
{
    int idx = blockIdx.x * blockDim.x + threadIdx.x;
    int d = idx & (D_ - 1);
    int l = (idx >> 10) & (L_ - 1);
    int b = idx >> 21;
    float acc = bias[d];
#pragma unroll
    for (int k = 0; k < 5; k++) {
        int ll = l + k - 2;
        if (ll >= 0 && ll < L_)
            acc = fmaf(x[((size_t)b * L_ + ll) * D_ + d], w[d * 5 + k], acc);
    }
    y[idx] = acc;
}

// ---------------- GLU + residual + LayerNorm ----------------
__global__ __launch_bounds__(256) void k_glu_ln(
    const float* __restrict__ x, const float* __restrict__ y2,
    const float* __restrict__ gbias, const float* __restrict__ lng,
    const float* __restrict__ lnb, float* __restrict__ out)
{
    int bl = blockIdx.x;
    int tid = threadIdx.x;
    int c = tid * 4;
    const float* xr = x + (size_t)bl * D_;
    const float* yr = y2 + (size_t)bl * 2 * D_;
    float4 xv = *(const float4*)(xr + c);
    float4 sv = *(const float4*)(yr + c);
    float4 gv = *(const float4*)(yr + D_ + c);
    float4 gb = *(const float4*)(gbias + c);
    float t0 = xv.x + sv.x * (1.f / (1.f + __expf(-(gv.x + gb.x))));
    float t1 = xv.y + sv.y * (1.f / (1.f + __expf(-(gv.y + gb.y))));
    float t2 = xv.z + sv.z * (1.f / (1.f + __expf(-(gv.z + gb.z))));
    float t3 = xv.w + sv.w * (1.f / (1.f + __expf(-(gv.w + gb.w))));

    __shared__ float red[256];
    red[tid] = t0 + t1 + t2 + t3;
    __syncthreads();
    for (int o = 128; o > 0; o >>= 1) { if (tid < o) red[tid] += red[tid + o]; __syncthreads(); }
    float m = red[0] * (1.f / 1024.f);
    __syncthreads();
    float d0 = t0 - m, d1 = t1 - m, d2 = t2 - m, d3 = t3 - m;
    red[tid] = d0 * d0 + d1 * d1 + d2 * d2 + d3 * d3;
    __syncthreads();
    for (int o = 128; o > 0; o >>= 1) { if (tid < o) red[tid] += red[tid + o]; __syncthreads(); }
    float inv = rsqrtf(red[0] * (1.f / 1024.f) + 1e-5f);
    float4 gg = *(const float4*)(lng + c);
    float4 bb = *(const float4*)(lnb + c);
    float4 o4;
    o4.x = d0 * inv * gg.x + bb.x;
    o4.y = d1 * inv * gg.y + bb.y;
    o4.z = d2 * inv * gg.z + bb.z;
    o4.w = d3 * inv * gg.w + bb.w;
    *(float4*)(out + (size_t)bl * D_ + c) = o4;
}

// ---------------- residual add + LayerNorm ----------------
__global__ __launch_bounds__(256) void k_add_ln(
    const float* __restrict__ x, const float* __restrict__ zv,
    const float* __restrict__ lng, const float* __restrict__ lnb,
    float* __restrict__ out)
{
    int bl = blockIdx.x;
    int tid = threadIdx.x;
    int c = tid * 4;
    float4 xv = *(const float4*)(x + (size_t)bl * D_ + c);
    float4 zz = *(const float4*)(zv + (size_t)bl * D_ + c);
    float t0 = xv.x + zz.x, t1 = xv.y + zz.y, t2 = xv.z + zz.z, t3 = xv.w + zz.w;

    __shared__ float red[256];
    red[tid] = t0 + t1 + t2 + t3;
    __syncthreads();
    for (int o = 128; o > 0; o >>= 1) { if (tid < o) red[tid] += red[tid + o]; __syncthreads(); }
    float m = red[0] * (1.f / 1024.f);
    __syncthreads();
    float d0 = t0 - m, d1 = t1 - m, d2 = t2 - m, d3 = t3 - m;
    red[tid] = d0 * d0 + d1 * d1 + d2 * d2 + d3 * d3;
    __syncthreads();
    for (int o = 128; o > 0; o >>= 1) { if (tid < o) red[tid] += red[tid + o]; __syncthreads(); }
    float inv = rsqrtf(red[0] * (1.f / 1024.f) + 1e-5f);
    float4 gg = *(const float4*)(lng + c);
    float4 bb = *(const float4*)(lnb + c);
    float4 o4;
    o4.x = d0 * inv * gg.x + bb.x;
    o4.y = d1 * inv * gg.y + bb.y;
    o4.z = d2 * inv * gg.z + bb.z;
    o4.w = d3 * inv * gg.w + bb.w;
    *(float4*)(out + (size_t)bl * D_ + c) = o4;
}

// ---------------- repack kv -> Kp [b][G][L][512], Vt [b][512][G*2048+L] ----------------
__global__ __launch_bounds__(256) void k_pack(
    const float* __restrict__ kv, float* __restrict__ kp, float* __restrict__ vt)
{
    int idx = blockIdx.x * blockDim.x + threadIdx.x;
    int d = idx & 63;
    int h16 = (idx >> 6) & 15;
    int l = (idx >> 10) & (L_ - 1);
    int b = idx >> 21;
    int G = h16 >> 3, h = h16 & 7;
    const float* base = kv + ((size_t)b * L_ + l) * 2048 + h16 * 128 + d;
    float kvk = base[0];
    float kvv = base[64];
    kp[(((size_t)(b * 2 + G) * L_ + l) * 512) + h * 64 + d] = kvk;
    vt[((size_t)b * 512 + h * 64 + d) * 4096 + G * 2048 + l] = kvv;
}

// ---------------- per-row softmax stats: (max, 1/sum(exp)) ----------------
__global__ __launch_bounds__(256) void k_rowstats(
    const float* __restrict__ S, float* __restrict__ rs)
{
    int l = blockIdx.x, G = blockIdx.y, bg = blockIdx.z;
    const float* row = S + ((size_t)bg * L_ + l) * 4096 + G * 2048;
    int tid = threadIdx.x;
    float v[8];
    float m = -INFINITY;
#pragma unroll
    for (int j = 0; j < 8; j++) { v[j] = row[tid + j * 256]; m = fmaxf(m, v[j]); }
    __shared__ float red[256];
    red[tid] = m;
    __syncthreads();
    for (int o = 128; o > 0; o >>= 1) { if (tid < o) red[tid] = fmaxf(red[tid], red[tid + o]); __syncthreads(); }
    m = red[0];
    __syncthreads();
    float s = 0.f;
#pragma unroll
    for (int j = 0; j < 8; j++) s += __expf(v[j] - m);
    red[tid] = s;
    __syncthreads();
    for (int o = 128; o > 0; o >>= 1) { if (tid < o) red[tid] += red[tid + o]; __syncthreads(); }
    if (tid == 0) {
        float* p = rs + ((size_t)(bg * L_ + l) * 2 + G) * 2;
        p[0] = m;
        p[1] = 1.f / red[0];
    }
}

// ---------------- host ----------------
static void fill1(Batch8& bt)
{
    for (int z = 0; z < 8; z++) {
        bt.offA[z] = bt.offB[z] = bt.offC[z] = bt.offS[z] = 0;
        bt.alpha[z] = 1.f;
    }
}

extern "C" void kernel_launch(void* const* d_in, const int* in_sizes, int n_in,
                              void* d_out, int out_size)
{
    (void)in_sizes; (void)n_in; (void)out_size;
    const int*   tok    = (const int*)  d_in[0];
    const float* ctab   = (const float*)d_in[1];
    const float* projw  = (const float*)d_in[2];
    const float* escale = (const float*)d_in[3];
    const float* dww    = (const float*)d_in[4];
    const float* dwb    = (const float*)d_in[5];
    const float* pww    = (const float*)d_in[6];
    const float* pwb    = (const float*)d_in[7];
    const float* gbias  = (const float*)d_in[8];
    const float* clng   = (const float*)d_in[9];
    const float* clnb   = (const float*)d_in[10];
    const float* qw     = (const float*)d_in[11];
    const float* kvw    = (const float*)d_in[12];
    const float* ow     = (const float*)d_in[13];
    const float* alng   = (const float*)d_in[14];
    const float* alnb   = (const float*)d_in[15];

    cudaFuncSetAttribute(gemm_mma, cudaFuncAttributeMaxDynamicSharedMemorySize, GEMM_SMEM);

    float *x, *t1, *t2, *q, *kp, *vt, *S, *rs;
    cudaGetSymbolAddress((void**)&x,  g_x);
    cudaGetSymbolAddress((void**)&t1, g_t1);
    cudaGetSymbolAddress((void**)&t2, g_t2);
    cudaGetSymbolAddress((void**)&q,  g_q);
    cudaGetSymbolAddress((void**)&kp, g_kp);
    cudaGetSymbolAddress((void**)&vt, g_vt);
    cudaGetSymbolAddress((void**)&S,  g_s);
    cudaGetSymbolAddress((void**)&rs, g_rs);

    k_embed<<<B_ * L_, 256>>>(tok, ctab, projw, escale, x);

    for (int i = 0; i < 2; i++) {
        // --- conv block ---
        k_dwconv<<<(B_ * L_ * D_) / 256, 256>>>(x, dww + (size_t)i * D_ * 5, dwb + i * D_, t1);

        Batch8 b1; fill1(b1);
        // pointwise: (4096 x 2048) = t1(4096x1024) * pw_w(2048x1024)^T + pw_b
        gemm_mma<<<dim3(8, 32, 1), 512, GEMM_SMEM>>>(t1, pww + (size_t)i * 2048 * 1024, t2,
                                                     pwb + i * 2048, nullptr,
                                                     1024, 1024, 1024, 2048, b1);

        k_glu_ln<<<B_ * L_, 256>>>(x, t2, gbias + i * D_, clng + i * D_, clnb + i * D_, x);

        // --- attention block ---
        gemm_mma<<<dim3(4, 32, 1), 512, GEMM_SMEM>>>(x, qw + (size_t)i * D_ * D_, q,
                                                     nullptr, nullptr, 1024, 1024, 1024, 1024, b1);
        gemm_mma<<<dim3(8, 32, 1), 512, GEMM_SMEM>>>(x, kvw + (size_t)i * 2048 * 1024, t2,
                                                     nullptr, nullptr, 1024, 1024, 1024, 2048, b1);

        k_pack<<<(B_ * L_ * 16 * 64) / 256, 256>>>(t2, kp, vt);

        // scores: per (b,g,G): Q_bg(2048x512) * Kp_bG(2048x512)^T * SCALE * fs[G]
        Batch8 bs; fill1(bs);
        for (int zz = 0; zz < 8; zz++) {
            int bg = zz >> 1, G = zz & 1;
            int b = bg >> 1, g = bg & 1;
            bs.offA[zz] = (long long)b * L_ * 1024 + g * 512;
            bs.offB[zz] = (long long)(b * 2 + G) * L_ * 512;
            bs.offC[zz] = (long long)bg * L_ * 4096 + G * 2048;
            bs.alpha[zz] = 0.125f * (G ? 2.0f : 1.0f);
        }
        gemm_mma<<<dim3(8, 16, 8), 512, GEMM_SMEM>>>(q, kp, S, nullptr, nullptr,
                                                     512, 1024, 512, 4096, bs);

        k_rowstats<<<dim3(L_, 2, 4), 256>>>(S, rs);

        // attention out: O(2048x512) = softmax(S)(2048x4096) * Vt(512x4096)^T
        Batch8 bo; fill1(bo);
        for (int zz = 0; zz < 4; zz++) {
            int b = zz >> 1, g = zz & 1;
            bo.offA[zz] = (long long)zz * L_ * 4096;
            bo.offB[zz] = (long long)b * 512 * 4096;
            bo.offC[zz] = (long long)b * L_ * 1024 + g * 512;
            bo.offS[zz] = (long long)zz * L_ * 4;
        }
        gemm_mma<<<dim3(2, 16, 4), 512, GEMM_SMEM>>>(S, vt, t1, nullptr, rs,
                                                     4096, 4096, 4096, 1024, bo);

        // out projection
        gemm_mma<<<dim3(4, 32, 1), 512, GEMM_SMEM>>>(t1, ow + (size_t)i * D_ * D_, q,
                                                     nullptr, nullptr, 1024, 1024, 1024, 1024, b1);

        float* dst = (i == 1) ? (float*)d_out : x;
        k_add_ln<<<B_ * L_, 256>>>(x, q, alng + i * D_, alnb + i * D_, dst);
    }
}

// round 4
// speedup vs baseline: 2.6639x; 1.0310x over previous
#include <cuda_runtime.h>
#include <cuda_bf16.h>
#include <math.h>
#include <stdint.h>

#define D_ 1024
#define L_ 2048
#define B_ 2

typedef __nv_bfloat16 bf16;

// GEMM: CTA 128x256, 512 thr, warps 4M x 4N (32x64 each), KC=32, 2-stage cp.async
#define STG_BYTES 49152
#define GEMM_SMEM (2 * STG_BYTES + 1024)

// ---------------- fp32 scratch ----------------
__device__ float g_x [B_ * L_ * D_];
__device__ float g_t2[B_ * L_ * 2 * D_];
__device__ float g_q [B_ * L_ * D_];
__device__ float g_s [4LL * L_ * 4096];

// ---------------- bf16 hi/lo planes ----------------
__device__ __align__(16) bf16 p_t1h[B_ * L_ * D_],       p_t1l[B_ * L_ * D_];
__device__ __align__(16) bf16 p_xh [B_ * L_ * D_],       p_xl [B_ * L_ * D_];
__device__ __align__(16) bf16 p_qh [B_ * L_ * D_],       p_ql [B_ * L_ * D_];
__device__ __align__(16) bf16 p_kph[B_ * 2 * L_ * 512],  p_kpl[B_ * 2 * L_ * 512];
__device__ __align__(16) bf16 p_vth[B_ * 512 * 2 * L_],  p_vtl[B_ * 512 * 2 * L_];
__device__ __align__(16) bf16 p_Ph [4LL * L_ * 4096],    p_Pl [4LL * L_ * 4096];
__device__ __align__(16) bf16 p_Wh [12 * 1024 * 1024],   p_Wl [12 * 1024 * 1024];

struct Batch8 {
    long long offA[8];
    long long offB[8];
    long long offC[8];
    float alpha[8];
};

// ---------------- helpers ----------------
__device__ __forceinline__ uint32_t smem_u32(const void* p) {
    uint32_t a;
    asm("{ .reg .u64 t; cvta.to.shared.u64 t, %1; cvt.u32.u64 %0, t; }" : "=r"(a) : "l"(p));
    return a;
}
__device__ __forceinline__ void split2(float a, float b, uint32_t& hi, uint32_t& lo) {
    uint32_t h;
    asm("cvt.rn.satfinite.bf16x2.f32 %0, %1, %2;" : "=r"(h) : "f"(b), "f"(a));
    float ra = a - __uint_as_float(h << 16);
    float rb = b - __uint_as_float(h & 0xffff0000u);
    uint32_t l;
    asm("cvt.rn.satfinite.bf16x2.f32 %0, %1, %2;" : "=r"(l) : "f"(rb), "f"(ra));
    hi = h; lo = l;
}
__device__ __forceinline__ void split1(float a, bf16& h, bf16& l) {
    h = __float2bfloat16_rn(a);
    l = __float2bfloat16_rn(a - __bfloat162float(h));
}
__device__ __forceinline__ void mma_bf16(float* c, const uint32_t* a, uint32_t b0, uint32_t b1) {
    asm volatile(
        "mma.sync.aligned.m16n8k16.row.col.f32.bf16.bf16.f32 "
        "{%0,%1,%2,%3}, {%4,%5,%6,%7}, {%8,%9}, {%0,%1,%2,%3};"
        : "+f"(c[0]), "+f"(c[1]), "+f"(c[2]), "+f"(c[3])
        : "r"(a[0]), "r"(a[1]), "r"(a[2]), "r"(a[3]), "r"(b0), "r"(b1));
}
__device__ __forceinline__ void cpa16(uint32_t s, const bf16* g) {
    asm volatile("cp.async.cg.shared.global [%0], [%1], 16;"
                 :: "r"(s), "l"(__cvta_generic_to_global((const void*)g)) : "memory");
}
__device__ __forceinline__ void ldm4(uint32_t addr, uint32_t* r) {
    asm volatile("ldmatrix.sync.aligned.m8n8.x4.shared.b16 {%0,%1,%2,%3}, [%4];"
                 : "=r"(r[0]), "=r"(r[1]), "=r"(r[2]), "=r"(r[3]) : "r"(addr));
}

// ---------------- plane-operand GEMM: C = alpha * A(MxK) * B(NxK)^T ----------------
// A = Ah + Al, B = Bh + Bl (bf16 hi/lo planes). 3-product split accumulation.
// Output: fp32 C (+bias) or bf16 planes Ch/Cl.
__global__ __launch_bounds__(512, 1) void gemm_pp(
    const bf16* __restrict__ Ah, const bf16* __restrict__ Al,
    const bf16* __restrict__ Bh, const bf16* __restrict__ Bl,
    float* __restrict__ C, bf16* __restrict__ Ch, bf16* __restrict__ Cl,
    const float* __restrict__ bias,
    int K, int lda, int ldb, int ldc, Batch8 bt)
{
    extern __shared__ char dsm[];
    uint32_t base = smem_u32(dsm);
    base = (base + 1023u) & ~1023u;

    const int z = blockIdx.z;
    const bf16* gAh = Ah + bt.offA[z];
    const bf16* gAl = Al + bt.offA[z];
    const bf16* gBh = Bh + bt.offB[z];
    const bf16* gBl = Bl + bt.offB[z];
    const float alpha = bt.alpha[z];

    const int tid = threadIdx.x;
    const int lane = tid & 31;
    const int wid = tid >> 5;
    const int wm = wid >> 2, wn = wid & 3;
    const int bm = blockIdx.y * 128, bn = blockIdx.x * 256;

    // cp.async chunk assignment: 3072 16B-chunks (A:1024, B:2048), 6 per thread
    const bf16* gsrc[6];
    uint32_t soff[6];
#pragma unroll
    for (int j = 0; j < 6; j++) {
        int c = tid + j * 512;
        bool isA = c < 1024;
        int cc = isA ? c : c - 1024;
        int row = cc >> 3, sub = cc & 7;
        const bf16* pl = (sub & 4) ? (isA ? gAl : gBl) : (isA ? gAh : gBh);
        int ld = isA ? lda : ldb;
        int r0 = isA ? bm : bn;
        gsrc[j] = pl + (size_t)(r0 + row) * ld + (sub & 3) * 8;
        soff[j] = base + (isA ? 0u : 16384u) + (uint32_t)row * 128u
                  + (((uint32_t)sub * 16u) ^ (((uint32_t)row & 7u) << 4));
    }

    // fragment addresses (SW128)
    const int rA = lane & 15, khA = lane >> 4;
    const uint32_t abase = base + (uint32_t)(wm * 32 + rA) * 128u;
    const uint32_t swA = ((uint32_t)rA & 7u) << 4;
    const int rBr = (lane & 7) + ((lane >> 4) << 3);
    const int khB = (lane >> 3) & 1;
    const uint32_t bbase = base + 16384u + (uint32_t)(wn * 64 + rBr) * 128u;
    const uint32_t swB = ((uint32_t)rBr & 7u) << 4;
    uint32_t ac[2][2], bc[2][2];
#pragma unroll
    for (int p = 0; p < 2; p++)
#pragma unroll
        for (int s = 0; s < 2; s++) {
            ac[p][s] = ((uint32_t)(p * 64 + (s * 2 + khA) * 16)) ^ swA;
            bc[p][s] = ((uint32_t)(p * 64 + (s * 2 + khB) * 16)) ^ swB;
        }

    float acc[2][8][4];
#pragma unroll
    for (int i = 0; i < 2; i++)
#pragma unroll
        for (int j = 0; j < 8; j++)
#pragma unroll
            for (int c = 0; c < 4; c++) acc[i][j][c] = 0.f;

    const int nk = K >> 5;

    // prologue: stage 0
#pragma unroll
    for (int j = 0; j < 6; j++) cpa16(soff[j], gsrc[j]);
    asm volatile("cp.async.commit_group;" ::: "memory");

    for (int kt = 0; kt < nk; kt++) {
        if (kt + 1 < nk) {
            uint32_t so = ((kt + 1) & 1) * (uint32_t)STG_BYTES;
            int k0 = (kt + 1) << 5;
#pragma unroll
            for (int j = 0; j < 6; j++) cpa16(soff[j] + so, gsrc[j] + k0);
            asm volatile("cp.async.commit_group;" ::: "memory");
            asm volatile("cp.async.wait_group 1;" ::: "memory");
        } else {
            asm volatile("cp.async.wait_group 0;" ::: "memory");
        }
        __syncthreads();
        const uint32_t so = (kt & 1) * (uint32_t)STG_BYTES;
#pragma unroll
        for (int s = 0; s < 2; s++) {
            uint32_t ah[2][4], al[2][4];
#pragma unroll
            for (int mb = 0; mb < 2; mb++) {
                ldm4(abase + so + mb * 2048 + ac[0][s], ah[mb]);
                ldm4(abase + so + mb * 2048 + ac[1][s], al[mb]);
            }
#pragma unroll
            for (int pr = 0; pr < 4; pr++) {
                uint32_t bh[4], bl[4];
                ldm4(bbase + so + pr * 2048 + bc[0][s], bh);
                ldm4(bbase + so + pr * 2048 + bc[1][s], bl);
#pragma unroll
                for (int nb2 = 0; nb2 < 2; nb2++) {
                    const int nb = pr * 2 + nb2;
#pragma unroll
                    for (int mb = 0; mb < 2; mb++) {
                        mma_bf16(acc[mb][nb], ah[mb], bh[nb2 * 2], bh[nb2 * 2 + 1]);
                        mma_bf16(acc[mb][nb], ah[mb], bl[nb2 * 2], bl[nb2 * 2 + 1]);
                        mma_bf16(acc[mb][nb], al[mb], bh[nb2 * 2], bh[nb2 * 2 + 1]);
                    }
                }
            }
        }
        __syncthreads();
    }

    // ---- epilogue ----
    const int qr = lane >> 2, qc = lane & 3;
    if (Ch) {
#pragma unroll
        for (int mb = 0; mb < 2; mb++) {
            const int row = bm + wm * 32 + mb * 16 + qr;
#pragma unroll
            for (int nb = 0; nb < 8; nb++) {
                const int col = bn + wn * 64 + nb * 8 + qc * 2;
                uint32_t h0, l0, h1, l1;
                split2(acc[mb][nb][0] * alpha, acc[mb][nb][1] * alpha, h0, l0);
                split2(acc[mb][nb][2] * alpha, acc[mb][nb][3] * alpha, h1, l1);
                const long long o0 = bt.offC[z] + (long long)row * ldc + col;
                const long long o1 = bt.offC[z] + (long long)(row + 8) * ldc + col;
                *(uint32_t*)(Ch + o0) = h0; *(uint32_t*)(Cl + o0) = l0;
                *(uint32_t*)(Ch + o1) = h1; *(uint32_t*)(Cl + o1) = l1;
            }
        }
    } else {
        float* Cz = C + bt.offC[z];
#pragma unroll
        for (int mb = 0; mb < 2; mb++) {
            const int row = bm + wm * 32 + mb * 16 + qr;
#pragma unroll
            for (int nb = 0; nb < 8; nb++) {
                const int col = bn + wn * 64 + nb * 8 + qc * 2;
                float2 v0, v1;
                v0.x = acc[mb][nb][0] * alpha;
                v0.y = acc[mb][nb][1] * alpha;
                v1.x = acc[mb][nb][2] * alpha;
                v1.y = acc[mb][nb][3] * alpha;
                if (bias) {
                    float2 bv = *(const float2*)(bias + col);
                    v0.x += bv.x; v0.y += bv.y;
                    v1.x += bv.x; v1.y += bv.y;
                }
                *(float2*)(Cz + (size_t)row * ldc + col) = v0;
                *(float2*)(Cz + (size_t)(row + 8) * ldc + col) = v1;
            }
        }
    }
}

// ---------------- weight split: fp32 -> hi/lo planes ----------------
__global__ __launch_bounds__(256) void k_split4(
    const float* __restrict__ w, bf16* __restrict__ h, bf16* __restrict__ l, int n4)
{
    int i = blockIdx.x * 256 + threadIdx.x;
    if (i < n4) {
        float4 v = ((const float4*)w)[i];
        uint32_t h0, l0, h1, l1;
        split2(v.x, v.y, h0, l0);
        split2(v.z, v.w, h1, l1);
        ((uint2*)h)[i] = make_uint2(h0, h1);
        ((uint2*)l)[i] = make_uint2(l0, l1);
    }
}

// ---------------- Julia embedding ----------------
__global__ __launch_bounds__(256) void k_embed(
    const int* __restrict__ tok, const float* __restrict__ ctab,
    const float* __restrict__ projw, const float* __restrict__ escale,
    float* __restrict__ x)
{
    int bl = blockIdx.x;
    int t = tok[bl];
    float cr = ctab[2 * t], ci = ctab[2 * t + 1];
    float f[16];
    float zr = 0.f, zi = 0.f;
#pragma unroll
    for (int s = 0; s < 8; s++) {
        float nr = zr * zr - zi * zi + cr;
        float ni = 2.f * zr * zi + ci;
        zr = nr; zi = ni;
        f[2 * s] = zr; f[2 * s + 1] = zi;
    }
    float es = escale[0];
    int d0 = threadIdx.x * 4;
    float4 o;
    float* op = &o.x;
#pragma unroll
    for (int j = 0; j < 4; j++) {
        const float* w = projw + (size_t)(d0 + j) * 16;
        float acc = 0.f;
#pragma unroll
        for (int k = 0; k < 16; k++) acc = fmaf(f[k], w[k], acc);
        op[j] = acc * es;
    }
    *(float4*)(x + (size_t)bl * D_ + d0) = o;
}

// ---------------- depthwise conv (K=5) -> planes ----------------
__global__ __launch_bounds__(256) void k_dwconv(
    const float* __restrict__ x, const float* __restrict__ w,
    const float* __restrict__ bias, bf16* __restrict__ yh, bf16* __restrict__ yl)
{
    int idx = blockIdx.x * blockDim.x + threadIdx.x;
    int d = idx & (D_ - 1);
    int l = (idx >> 10) & (L_ - 1);
    int b = idx >> 21;
    float acc = bias[d];
#pragma unroll
    for (int k = 0; k < 5; k++) {
        int ll = l + k - 2;
        if (ll >= 0 && ll < L_)
            acc = fmaf(x[((size_t)b * L_ + ll) * D_ + d], w[d * 5 + k], acc);
    }
    bf16 h, lo;
    split1(acc, h, lo);
    yh[idx] = h; yl[idx] = lo;
}

// ---------------- GLU + residual + LayerNorm -> fp32 x + planes ----------------
__global__ __launch_bounds__(256) void k_glu_ln(
    const float* __restrict__ x, const float* __restrict__ y2,
    const float* __restrict__ gbias, const float* __restrict__ lng,
    const float* __restrict__ lnb, float* __restrict__ out,
    bf16* __restrict__ oh, bf16* __restrict__ ol)
{
    int bl = blockIdx.x;
    int tid = threadIdx.x;
    int c = tid * 4;
    const float* xr = x + (size_t)bl * D_;
    const float* yr = y2 + (size_t)bl * 2 * D_;
    float4 xv = *(const float4*)(xr + c);
    float4 sv = *(const float4*)(yr + c);
    float4 gv = *(const float4*)(yr + D_ + c);
    float4 gb = *(const float4*)(gbias + c);
    float t0 = xv.x + sv.x * (1.f / (1.f + __expf(-(gv.x + gb.x))));
    float t1 = xv.y + sv.y * (1.f / (1.f + __expf(-(gv.y + gb.y))));
    float t2 = xv.z + sv.z * (1.f / (1.f + __expf(-(gv.z + gb.z))));
    float t3 = xv.w + sv.w * (1.f / (1.f + __expf(-(gv.w + gb.w))));

    __shared__ float red[256];
    red[tid] = t0 + t1 + t2 + t3;
    __syncthreads();
    for (int o = 128; o > 0; o >>= 1) { if (tid < o) red[tid] += red[tid + o]; __syncthreads(); }
    float m = red[0] * (1.f / 1024.f);
    __syncthreads();
    float d0 = t0 - m, d1 = t1 - m, d2 = t2 - m, d3 = t3 - m;
    red[tid] = d0 * d0 + d1 * d1 + d2 * d2 + d3 * d3;
    __syncthreads();
    for (int o = 128; o > 0; o >>= 1) { if (tid < o) red[tid] += red[tid + o]; __syncthreads(); }
    float inv = rsqrtf(red[0] * (1.f / 1024.f) + 1e-5f);
    float4 gg = *(const float4*)(lng + c);
    float4 bb = *(const float4*)(lnb + c);
    float4 o4;
    o4.x = d0 * inv * gg.x + bb.x;
    o4.y = d1 * inv * gg.y + bb.y;
    o4.z = d2 * inv * gg.z + bb.z;
    o4.w = d3 * inv * gg.w + bb.w;
    size_t off = (size_t)bl * D_ + c;
    *(float4*)(out + off) = o4;
    uint32_t h0, l0, h1, l1;
    split2(o4.x, o4.y, h0, l0);
    split2(o4.z, o4.w, h1, l1);
    *(uint2*)(oh + off) = make_uint2(h0, h1);
    *(uint2*)(ol + off) = make_uint2(l0, l1);
}

// ---------------- residual add + LayerNorm (planes optional) ----------------
__global__ __launch_bounds__(256) void k_add_ln(
    const float* __restrict__ x, const float* __restrict__ zv,
    const float* __restrict__ lng, const float* __restrict__ lnb,
    float* __restrict__ out, bf16* __restrict__ oh, bf16* __restrict__ ol)
{
    int bl = blockIdx.x;
    int tid = threadIdx.x;
    int c = tid * 4;
    float4 xv = *(const float4*)(x + (size_t)bl * D_ + c);
    float4 zz = *(const float4*)(zv + (size_t)bl * D_ + c);
    float t0 = xv.x + zz.x, t1 = xv.y + zz.y, t2 = xv.z + zz.z, t3 = xv.w + zz.w;

    __shared__ float red[256];
    red[tid] = t0 + t1 + t2 + t3;
    __syncthreads();
    for (int o = 128; o > 0; o >>= 1) { if (tid < o) red[tid] += red[tid + o]; __syncthreads(); }
    float m = red[0] * (1.f / 1024.f);
    __syncthreads();
    float d0 = t0 - m, d1 = t1 - m, d2 = t2 - m, d3 = t3 - m;
    red[tid] = d0 * d0 + d1 * d1 + d2 * d2 + d3 * d3;
    __syncthreads();
    for (int o = 128; o > 0; o >>= 1) { if (tid < o) red[tid] += red[tid + o]; __syncthreads(); }
    float inv = rsqrtf(red[0] * (1.f / 1024.f) + 1e-5f);
    float4 gg = *(const float4*)(lng + c);
    float4 bb = *(const float4*)(lnb + c);
    float4 o4;
    o4.x = d0 * inv * gg.x + bb.x;
    o4.y = d1 * inv * gg.y + bb.y;
    o4.z = d2 * inv * gg.z + bb.z;
    o4.w = d3 * inv * gg.w + bb.w;
    size_t off = (size_t)bl * D_ + c;
    *(float4*)(out + off) = o4;
    if (oh) {
        uint32_t h0, l0, h1, l1;
        split2(o4.x, o4.y, h0, l0);
        split2(o4.z, o4.w, h1, l1);
        *(uint2*)(oh + off) = make_uint2(h0, h1);
        *(uint2*)(ol + off) = make_uint2(l0, l1);
    }
}

// ---------------- repack kv -> Kp planes, Vt planes ----------------
__global__ __launch_bounds__(256) void k_pack(
    const float* __restrict__ kv, bf16* __restrict__ kph, bf16* __restrict__ kpl,
    bf16* __restrict__ vth, bf16* __restrict__ vtl)
{
    int idx = blockIdx.x * blockDim.x + threadIdx.x;
    int d = idx & 63;
    int h16 = (idx >> 6) & 15;
    int l = (idx >> 10) & (L_ - 1);
    int b = idx >> 21;
    int G = h16 >> 3, h = h16 & 7;
    const float* base = kv + ((size_t)b * L_ + l) * 2048 + h16 * 128 + d;
    float kvk = base[0];
    float kvv = base[64];
    bf16 hh, ll;
    split1(kvk, hh, ll);
    size_t ko = (((size_t)(b * 2 + G) * L_ + l) * 512) + h * 64 + d;
    kph[ko] = hh; kpl[ko] = ll;
    split1(kvv, hh, ll);
    size_t vo = ((size_t)b * 512 + h * 64 + d) * 4096 + G * 2048 + l;
    vth[vo] = hh; vtl[vo] = ll;
}

// ---------------- row softmax: stats + exp + split -> P planes ----------------
__global__ __launch_bounds__(256) void k_rowsoft(
    const float* __restrict__ S, bf16* __restrict__ Ph, bf16* __restrict__ Pl)
{
    const int l = blockIdx.x, G = blockIdx.y, bg = blockIdx.z;
    const size_t roff = ((size_t)bg * L_ + l) * 4096 + (size_t)G * 2048;
    const int tid = threadIdx.x;
    float v[8];
    *(float4*)(v)     = *(const float4*)(S + roff + tid * 8);
    *(float4*)(v + 4) = *(const float4*)(S + roff + tid * 8 + 4);
    float m = v[0];
#pragma unroll
    for (int j = 1; j < 8; j++) m = fmaxf(m, v[j]);
    __shared__ float red[256];
    red[tid] = m;
    __syncthreads();
    for (int o = 128; o > 0; o >>= 1) { if (tid < o) red[tid] = fmaxf(red[tid], red[tid + o]); __syncthreads(); }
    m = red[0];
    __syncthreads();
    float e[8];
    float s = 0.f;
#pragma unroll
    for (int j = 0; j < 8; j++) { e[j] = __expf(v[j] - m); s += e[j]; }
    red[tid] = s;
    __syncthreads();
    for (int o = 128; o > 0; o >>= 1) { if (tid < o) red[tid] += red[tid + o]; __syncthreads(); }
    float inv = 1.f / red[0];
    uint4 ho, lo4;
    split2(e[0] * inv, e[1] * inv, ho.x, lo4.x);
    split2(e[2] * inv, e[3] * inv, ho.y, lo4.y);
    split2(e[4] * inv, e[5] * inv, ho.z, lo4.z);
    split2(e[6] * inv, e[7] * inv, ho.w, lo4.w);
    *(uint4*)(Ph + roff + tid * 8) = ho;
    *(uint4*)(Pl + roff + tid * 8) = lo4;
}

// ---------------- host ----------------
static void fill1(Batch8& bt)
{
    for (int z = 0; z < 8; z++) {
        bt.offA[z] = bt.offB[z] = bt.offC[z] = 0;
        bt.alpha[z] = 1.f;
    }
}

extern "C" void kernel_launch(void* const* d_in, const int* in_sizes, int n_in,
                              void* d_out, int out_size)
{
    (void)in_sizes; (void)n_in; (void)out_size;
    const int*   tok    = (const int*)  d_in[0];
    const float* ctab   = (const float*)d_in[1];
    const float* projw  = (const float*)d_in[2];
    const float* escale = (const float*)d_in[3];
    const float* dww    = (const float*)d_in[4];
    const float* dwb    = (const float*)d_in[5];
    const float* pww    = (const float*)d_in[6];
    const float* pwb    = (const float*)d_in[7];
    const float* gbias  = (const float*)d_in[8];
    const float* clng   = (const float*)d_in[9];
    const float* clnb   = (const float*)d_in[10];
    const float* qw     = (const float*)d_in[11];
    const float* kvw    = (const float*)d_in[12];
    const float* ow     = (const float*)d_in[13];
    const float* alng   = (const float*)d_in[14];
    const float* alnb   = (const float*)d_in[15];

    cudaFuncSetAttribute(gemm_pp, cudaFuncAttributeMaxDynamicSharedMemorySize, GEMM_SMEM);

    float *x, *t2, *q, *S;
    cudaGetSymbolAddress((void**)&x,  g_x);
    cudaGetSymbolAddress((void**)&t2, g_t2);
    cudaGetSymbolAddress((void**)&q,  g_q);
    cudaGetSymbolAddress((void**)&S,  g_s);
    bf16 *t1h, *t1l, *xh, *xl, *qh, *ql, *kph, *kpl, *vth, *vtl, *Ph, *Pl, *Wh, *Wl;
    cudaGetSymbolAddress((void**)&t1h, p_t1h); cudaGetSymbolAddress((void**)&t1l, p_t1l);
    cudaGetSymbolAddress((void**)&xh,  p_xh);  cudaGetSymbolAddress((void**)&xl,  p_xl);
    cudaGetSymbolAddress((void**)&qh,  p_qh);  cudaGetSymbolAddress((void**)&ql,  p_ql);
    cudaGetSymbolAddress((void**)&kph, p_kph); cudaGetSymbolAddress((void**)&kpl, p_kpl);
    cudaGetSymbolAddress((void**)&vth, p_vth); cudaGetSymbolAddress((void**)&vtl, p_vtl);
    cudaGetSymbolAddress((void**)&Ph,  p_Ph);  cudaGetSymbolAddress((void**)&Pl,  p_Pl);
    cudaGetSymbolAddress((void**)&Wh,  p_Wh);  cudaGetSymbolAddress((void**)&Wl,  p_Wl);

    // weight plane offsets: pw@0(4M), qw@4M(2M), kvw@6M(4M), ow@10M(2M)
    const long long OPW = 0, OQW = 4194304, OKV = 6291456, OOW = 10485760;
    k_split4<<<4096, 256>>>(pww, Wh + OPW, Wl + OPW, 1048576);
    k_split4<<<2048, 256>>>(qw,  Wh + OQW, Wl + OQW, 524288);
    k_split4<<<4096, 256>>>(kvw, Wh + OKV, Wl + OKV, 1048576);
    k_split4<<<2048, 256>>>(ow,  Wh + OOW, Wl + OOW, 524288);

    k_embed<<<B_ * L_, 256>>>(tok, ctab, projw, escale, x);

    for (int i = 0; i < 2; i++) {
        // --- conv block ---
        k_dwconv<<<(B_ * L_ * D_) / 256, 256>>>(x, dww + (size_t)i * D_ * 5, dwb + i * D_,
                                                t1h, t1l);

        Batch8 b1; fill1(b1);
        // pointwise: t2(4096x2048) = t1(4096x1024) * pw_w(2048x1024)^T + pw_b
        gemm_pp<<<dim3(8, 32, 1), 512, GEMM_SMEM>>>(
            t1h, t1l, Wh + OPW + (long long)i * 2097152, Wl + OPW + (long long)i * 2097152,
            t2, nullptr, nullptr, pwb + i * 2048, 1024, 1024, 1024, 2048, b1);

        k_glu_ln<<<B_ * L_, 256>>>(x, t2, gbias + i * D_, clng + i * D_, clnb + i * D_,
                                   x, xh, xl);

        // --- attention block ---
        // q (planes out)
        gemm_pp<<<dim3(4, 32, 1), 512, GEMM_SMEM>>>(
            xh, xl, Wh + OQW + (long long)i * 1048576, Wl + OQW + (long long)i * 1048576,
            nullptr, qh, ql, nullptr, 1024, 1024, 1024, 1024, b1);
        // kv (fp32 out)
        gemm_pp<<<dim3(8, 32, 1), 512, GEMM_SMEM>>>(
            xh, xl, Wh + OKV + (long long)i * 2097152, Wl + OKV + (long long)i * 2097152,
            t2, nullptr, nullptr, nullptr, 1024, 1024, 1024, 2048, b1);

        k_pack<<<(B_ * L_ * 16 * 64) / 256, 256>>>(t2, kph, kpl, vth, vtl);

        // scores: per (b,g,G): S = Q_bg(2048x512) * Kp_bG(2048x512)^T * SCALE * fs[G]
        Batch8 bs; fill1(bs);
        for (int zz = 0; zz < 8; zz++) {
            int bg = zz >> 1, G = zz & 1;
            int b = bg >> 1, g = bg & 1;
            bs.offA[zz] = (long long)b * L_ * 1024 + g * 512;
            bs.offB[zz] = (long long)(b * 2 + G) * L_ * 512;
            bs.offC[zz] = (long long)bg * L_ * 4096 + G * 2048;
            bs.alpha[zz] = 0.125f * (G ? 2.0f : 1.0f);
        }
        gemm_pp<<<dim3(8, 16, 8), 512, GEMM_SMEM>>>(
            qh, ql, kph, kpl, S, nullptr, nullptr, nullptr, 512, 1024, 512, 4096, bs);

        k_rowsoft<<<dim3(L_, 2, 4), 256>>>(S, Ph, Pl);

        // attention out: O(2048x512) = P(2048x4096) * Vt(512x4096)^T -> t1 planes
        Batch8 bo; fill1(bo);
        for (int zz = 0; zz < 4; zz++) {
            int b = zz >> 1, g = zz & 1;
            bo.offA[zz] = (long long)zz * L_ * 4096;
            bo.offB[zz] = (long long)b * 512 * 4096;
            bo.offC[zz] = (long long)b * L_ * 1024 + g * 512;
        }
        gemm_pp<<<dim3(2, 16, 4), 512, GEMM_SMEM>>>(
            Ph, Pl, vth, vtl, nullptr, t1h, t1l, nullptr, 4096, 4096, 4096, 1024, bo);

        // out projection (fp32 into q buffer)
        gemm_pp<<<dim3(4, 32, 1), 512, GEMM_SMEM>>>(
            t1h, t1l, Wh + OOW + (long long)i * 1048576, Wl + OOW + (long long)i * 1048576,
            q, nullptr, nullptr, nullptr, 1024, 1024, 1024, 1024, b1);

        float* dst = (i == 1) ? (float*)d_out : x;
        bf16* oh = (i == 1) ? nullptr : nullptr;  // next layer consumes x via dwconv (fp32)
        k_add_ln<<<B_ * L_, 256>>>(x, q, alng + i * D_, alnb + i * D_, dst, oh, nullptr);
    }
}

// round 5
// speedup vs baseline: 2.7368x; 1.0274x over previous
#include <cuda_runtime.h>
#include <cuda_bf16.h>
#include <math.h>
#include <stdint.h>

#define D_ 1024
#define L_ 2048
#define B_ 2

typedef __nv_bfloat16 bf16;

// GEMM: CTA 128x256, 512 thr, warps 4M x 4N (32x64 each), KC=32, 2-stage cp.async
#define STG_BYTES 49152
#define GEMM_SMEM (2 * STG_BYTES + 1024)

// ---------------- fp32 scratch ----------------
__device__ float g_x [B_ * L_ * D_];
__device__ float g_t2[B_ * L_ * 2 * D_];
__device__ float g_q [B_ * L_ * D_];
__device__ float g_s [4LL * L_ * 4096];

// ---------------- bf16 hi/lo planes ----------------
__device__ __align__(16) bf16 p_t1h[B_ * L_ * D_],       p_t1l[B_ * L_ * D_];
__device__ __align__(16) bf16 p_xh [B_ * L_ * D_],       p_xl [B_ * L_ * D_];
__device__ __align__(16) bf16 p_qh [B_ * L_ * D_],       p_ql [B_ * L_ * D_];
__device__ __align__(16) bf16 p_kph[B_ * 2 * L_ * 512],  p_kpl[B_ * 2 * L_ * 512];
__device__ __align__(16) bf16 p_vth[B_ * 512 * 2 * L_],  p_vtl[B_ * 512 * 2 * L_];
__device__ __align__(16) bf16 p_Ph [4LL * L_ * 4096],    p_Pl [4LL * L_ * 4096];
__device__ __align__(16) bf16 p_Wh [12 * 1024 * 1024],   p_Wl [12 * 1024 * 1024];

struct Batch8 {
    long long offA[8];
    long long offB[8];
    long long offC[8];
    float alpha[8];
};

// ---------------- helpers ----------------
__device__ __forceinline__ uint32_t smem_u32(const void* p) {
    uint32_t a;
    asm("{ .reg .u64 t; cvta.to.shared.u64 t, %1; cvt.u32.u64 %0, t; }" : "=r"(a) : "l"(p));
    return a;
}
__device__ __forceinline__ void split2(float a, float b, uint32_t& hi, uint32_t& lo) {
    uint32_t h;
    asm("cvt.rn.satfinite.bf16x2.f32 %0, %1, %2;" : "=r"(h) : "f"(b), "f"(a));
    float ra = a - __uint_as_float(h << 16);
    float rb = b - __uint_as_float(h & 0xffff0000u);
    uint32_t l;
    asm("cvt.rn.satfinite.bf16x2.f32 %0, %1, %2;" : "=r"(l) : "f"(rb), "f"(ra));
    hi = h; lo = l;
}
__device__ __forceinline__ void split1(float a, bf16& h, bf16& l) {
    h = __float2bfloat16_rn(a);
    l = __float2bfloat16_rn(a - __bfloat162float(h));
}
__device__ __forceinline__ void mma_bf16(float* c, const uint32_t* a, uint32_t b0, uint32_t b1) {
    asm volatile(
        "mma.sync.aligned.m16n8k16.row.col.f32.bf16.bf16.f32 "
        "{%0,%1,%2,%3}, {%4,%5,%6,%7}, {%8,%9}, {%0,%1,%2,%3};"
        : "+f"(c[0]), "+f"(c[1]), "+f"(c[2]), "+f"(c[3])
        : "r"(a[0]), "r"(a[1]), "r"(a[2]), "r"(a[3]), "r"(b0), "r"(b1));
}
__device__ __forceinline__ void cpa16(uint32_t s, const bf16* g) {
    asm volatile("cp.async.cg.shared.global [%0], [%1], 16;"
                 :: "r"(s), "l"(__cvta_generic_to_global((const void*)g)) : "memory");
}
__device__ __forceinline__ void ldm4(uint32_t addr, uint32_t* r) {
    asm volatile("ldmatrix.sync.aligned.m8n8.x4.shared.b16 {%0,%1,%2,%3}, [%4];"
                 : "=r"(r[0]), "=r"(r[1]), "=r"(r[2]), "=r"(r[3]) : "r"(addr));
}

// ---------------- plane-operand GEMM: C = alpha * A(MxK) * B(NxK)^T ----------------
// A = Ah + Al, B = Bh + Bl (bf16 hi/lo planes). 3-product split accumulation,
// issued product-major so accumulator RAW distance is 8 MMAs.
__global__ __launch_bounds__(512, 1) void gemm_pp(
    const bf16* __restrict__ Ah, const bf16* __restrict__ Al,
    const bf16* __restrict__ Bh, const bf16* __restrict__ Bl,
    float* __restrict__ C, bf16* __restrict__ Ch, bf16* __restrict__ Cl,
    const float* __restrict__ bias,
    int K, int lda, int ldb, int ldc, Batch8 bt)
{
    extern __shared__ char dsm[];
    uint32_t base = smem_u32(dsm);
    base = (base + 1023u) & ~1023u;

    const int z = blockIdx.z;
    const bf16* gAh = Ah + bt.offA[z];
    const bf16* gAl = Al + bt.offA[z];
    const bf16* gBh = Bh + bt.offB[z];
    const bf16* gBl = Bl + bt.offB[z];
    const float alpha = bt.alpha[z];

    const int tid = threadIdx.x;
    const int lane = tid & 31;
    const int wid = tid >> 5;
    const int wm = wid >> 2, wn = wid & 3;
    const int bm = blockIdx.y * 128, bn = blockIdx.x * 256;

    // cp.async chunk assignment: 3072 16B-chunks (A:1024, B:2048), 6 per thread
    const bf16* gsrc[6];
    uint32_t soff[6];
#pragma unroll
    for (int j = 0; j < 6; j++) {
        int c = tid + j * 512;
        bool isA = c < 1024;
        int cc = isA ? c : c - 1024;
        int row = cc >> 3, sub = cc & 7;
        const bf16* pl = (sub & 4) ? (isA ? gAl : gBl) : (isA ? gAh : gBh);
        int ld = isA ? lda : ldb;
        int r0 = isA ? bm : bn;
        gsrc[j] = pl + (size_t)(r0 + row) * ld + (sub & 3) * 8;
        soff[j] = base + (isA ? 0u : 16384u) + (uint32_t)row * 128u
                  + (((uint32_t)sub * 16u) ^ (((uint32_t)row & 7u) << 4));
    }

    // fragment addresses (SW128)
    const int rA = lane & 15, khA = lane >> 4;
    const uint32_t abase = base + (uint32_t)(wm * 32 + rA) * 128u;
    const uint32_t swA = ((uint32_t)rA & 7u) << 4;
    const int rBr = (lane & 7) + ((lane >> 4) << 3);
    const int khB = (lane >> 3) & 1;
    const uint32_t bbase = base + 16384u + (uint32_t)(wn * 64 + rBr) * 128u;
    const uint32_t swB = ((uint32_t)rBr & 7u) << 4;
    uint32_t ac[2][2], bc[2][2];
#pragma unroll
    for (int p = 0; p < 2; p++)
#pragma unroll
        for (int s = 0; s < 2; s++) {
            ac[p][s] = ((uint32_t)(p * 64 + (s * 2 + khA) * 16)) ^ swA;
            bc[p][s] = ((uint32_t)(p * 64 + (s * 2 + khB) * 16)) ^ swB;
        }

    float acc[2][8][4];
#pragma unroll
    for (int i = 0; i < 2; i++)
#pragma unroll
        for (int j = 0; j < 8; j++)
#pragma unroll
            for (int c = 0; c < 4; c++) acc[i][j][c] = 0.f;

    const int nk = K >> 5;

    // prologue: stage 0
#pragma unroll
    for (int j = 0; j < 6; j++) cpa16(soff[j], gsrc[j]);
    asm volatile("cp.async.commit_group;" ::: "memory");

    for (int kt = 0; kt < nk; kt++) {
        if (kt + 1 < nk) {
            uint32_t so = ((kt + 1) & 1) * (uint32_t)STG_BYTES;
            int k0 = (kt + 1) << 5;
#pragma unroll
            for (int j = 0; j < 6; j++) cpa16(soff[j] + so, gsrc[j] + k0);
            asm volatile("cp.async.commit_group;" ::: "memory");
            asm volatile("cp.async.wait_group 1;" ::: "memory");
        } else {
            asm volatile("cp.async.wait_group 0;" ::: "memory");
        }
        __syncthreads();
        const uint32_t so = (kt & 1) * (uint32_t)STG_BYTES;
#pragma unroll
        for (int s = 0; s < 2; s++) {
            uint32_t ah[2][4], al[2][4];
#pragma unroll
            for (int mb = 0; mb < 2; mb++) {
                ldm4(abase + so + mb * 2048 + ac[0][s], ah[mb]);
                ldm4(abase + so + mb * 2048 + ac[1][s], al[mb]);
            }
#pragma unroll
            for (int half = 0; half < 2; half++) {
                uint32_t bh[2][4], bl[2][4];
#pragma unroll
                for (int p2 = 0; p2 < 2; p2++) {
                    const int pr = half * 2 + p2;
                    ldm4(bbase + so + pr * 2048 + bc[0][s], bh[p2]);
                    ldm4(bbase + so + pr * 2048 + bc[1][s], bl[p2]);
                }
                // product 1: Ah x Bh  (8 MMAs, all distinct accumulators)
#pragma unroll
                for (int p2 = 0; p2 < 2; p2++)
#pragma unroll
                    for (int nb2 = 0; nb2 < 2; nb2++)
#pragma unroll
                        for (int mb = 0; mb < 2; mb++)
                            mma_bf16(acc[mb][(half * 2 + p2) * 2 + nb2],
                                     ah[mb], bh[p2][nb2 * 2], bh[p2][nb2 * 2 + 1]);
                // product 2: Ah x Bl
#pragma unroll
                for (int p2 = 0; p2 < 2; p2++)
#pragma unroll
                    for (int nb2 = 0; nb2 < 2; nb2++)
#pragma unroll
                        for (int mb = 0; mb < 2; mb++)
                            mma_bf16(acc[mb][(half * 2 + p2) * 2 + nb2],
                                     ah[mb], bl[p2][nb2 * 2], bl[p2][nb2 * 2 + 1]);
                // product 3: Al x Bh
#pragma unroll
                for (int p2 = 0; p2 < 2; p2++)
#pragma unroll
                    for (int nb2 = 0; nb2 < 2; nb2++)
#pragma unroll
                        for (int mb = 0; mb < 2; mb++)
                            mma_bf16(acc[mb][(half * 2 + p2) * 2 + nb2],
                                     al[mb], bh[p2][nb2 * 2], bh[p2][nb2 * 2 + 1]);
            }
        }
        __syncthreads();
    }

    // ---- epilogue ----
    const int qr = lane >> 2, qc = lane & 3;
    if (Ch) {
#pragma unroll
        for (int mb = 0; mb < 2; mb++) {
            const int row = bm + wm * 32 + mb * 16 + qr;
#pragma unroll
            for (int nb = 0; nb < 8; nb++) {
                const int col = bn + wn * 64 + nb * 8 + qc * 2;
                uint32_t h0, l0, h1, l1;
                split2(acc[mb][nb][0] * alpha, acc[mb][nb][1] * alpha, h0, l0);
                split2(acc[mb][nb][2] * alpha, acc[mb][nb][3] * alpha, h1, l1);
                const long long o0 = bt.offC[z] + (long long)row * ldc + col;
                const long long o1 = bt.offC[z] + (long long)(row + 8) * ldc + col;
                *(uint32_t*)(Ch + o0) = h0; *(uint32_t*)(Cl + o0) = l0;
                *(uint32_t*)(Ch + o1) = h1; *(uint32_t*)(Cl + o1) = l1;
            }
        }
    } else {
        float* Cz = C + bt.offC[z];
#pragma unroll
        for (int mb = 0; mb < 2; mb++) {
            const int row = bm + wm * 32 + mb * 16 + qr;
#pragma unroll
            for (int nb = 0; nb < 8; nb++) {
                const int col = bn + wn * 64 + nb * 8 + qc * 2;
                float2 v0, v1;
                v0.x = acc[mb][nb][0] * alpha;
                v0.y = acc[mb][nb][1] * alpha;
                v1.x = acc[mb][nb][2] * alpha;
                v1.y = acc[mb][nb][3] * alpha;
                if (bias) {
                    float2 bv = *(const float2*)(bias + col);
                    v0.x += bv.x; v0.y += bv.y;
                    v1.x += bv.x; v1.y += bv.y;
                }
                *(float2*)(Cz + (size_t)row * ldc + col) = v0;
                *(float2*)(Cz + (size_t)(row + 8) * ldc + col) = v1;
            }
        }
    }
}

// ---------------- weight split: fp32 -> hi/lo planes ----------------
__global__ __launch_bounds__(256) void k_split4(
    const float* __restrict__ w, bf16* __restrict__ h, bf16* __restrict__ l, int n4)
{
    int i = blockIdx.x * 256 + threadIdx.x;
    if (i < n4) {
        float4 v = ((const float4*)w)[i];
        uint32_t h0, l0, h1, l1;
        split2(v.x, v.y, h0, l0);
        split2(v.z, v.w, h1, l1);
        ((uint2*)h)[i] = make_uint2(h0, h1);
        ((uint2*)l)[i] = make_uint2(l0, l1);
    }
}

// ---------------- Julia embedding ----------------
__global__ __launch_bounds__(256) void k_embed(
    const int* __restrict__ tok, const float* __restrict__ ctab,
    const float* __restrict__ projw, const float* __restrict__ escale,
    float* __restrict__ x)
{
    int bl = blockIdx.x;
    int t = tok[bl];
    float cr = ctab[2 * t], ci = ctab[2 * t + 1];
    float f[16];
    float zr = 0.f, zi = 0.f;
#pragma unroll
    for (int s = 0; s < 8; s++) {
        float nr = zr * zr - zi * zi + cr;
        float ni = 2.f * zr * zi + ci;
        zr = nr; zi = ni;
        f[2 * s] = zr; f[2 * s + 1] = zi;
    }
    float es = escale[0];
    int d0 = threadIdx.x * 4;
    float4 o;
    float* op = &o.x;
#pragma unroll
    for (int j = 0; j < 4; j++) {
        const float* w = projw + (size_t)(d0 + j) * 16;
        float acc = 0.f;
#pragma unroll
        for (int k = 0; k < 16; k++) acc = fmaf(f[k], w[k], acc);
        op[j] = acc * es;
    }
    *(float4*)(x + (size_t)bl * D_ + d0) = o;
}

// ---------------- depthwise conv (K=5) -> planes ----------------
__global__ __launch_bounds__(256) void k_dwconv(
    const float* __restrict__ x, const float* __restrict__ w,
    const float* __restrict__ bias, bf16* __restrict__ yh, bf16* __restrict__ yl)
{
    int idx = blockIdx.x * blockDim.x + threadIdx.x;
    int d = idx & (D_ - 1);
    int l = (idx >> 10) & (L_ - 1);
    int b = idx >> 21;
    float acc = bias[d];
#pragma unroll
    for (int k = 0; k < 5; k++) {
        int ll = l + k - 2;
        if (ll >= 0 && ll < L_)
            acc = fmaf(x[((size_t)b * L_ + ll) * D_ + d], w[d * 5 + k], acc);
    }
    bf16 h, lo;
    split1(acc, h, lo);
    yh[idx] = h; yl[idx] = lo;
}

// ---------------- GLU + residual + LayerNorm -> fp32 x + planes ----------------
__global__ __launch_bounds__(256) void k_glu_ln(
    const float* __restrict__ x, const float* __restrict__ y2,
    const float* __restrict__ gbias, const float* __restrict__ lng,
    const float* __restrict__ lnb, float* __restrict__ out,
    bf16* __restrict__ oh, bf16* __restrict__ ol)
{
    int bl = blockIdx.x;
    int tid = threadIdx.x;
    int c = tid * 4;
    const float* xr = x + (size_t)bl * D_;
    const float* yr = y2 + (size_t)bl * 2 * D_;
    float4 xv = *(const float4*)(xr + c);
    float4 sv = *(const float4*)(yr + c);
    float4 gv = *(const float4*)(yr + D_ + c);
    float4 gb = *(const float4*)(gbias + c);
    float t0 = xv.x + sv.x * (1.f / (1.f + __expf(-(gv.x + gb.x))));
    float t1 = xv.y + sv.y * (1.f / (1.f + __expf(-(gv.y + gb.y))));
    float t2 = xv.z + sv.z * (1.f / (1.f + __expf(-(gv.z + gb.z))));
    float t3 = xv.w + sv.w * (1.f / (1.f + __expf(-(gv.w + gb.w))));

    __shared__ float red[256];
    red[tid] = t0 + t1 + t2 + t3;
    __syncthreads();
    for (int o = 128; o > 0; o >>= 1) { if (tid < o) red[tid] += red[tid + o]; __syncthreads(); }
    float m = red[0] * (1.f / 1024.f);
    __syncthreads();
    float d0 = t0 - m, d1 = t1 - m, d2 = t2 - m, d3 = t3 - m;
    red[tid] = d0 * d0 + d1 * d1 + d2 * d2 + d3 * d3;
    __syncthreads();
    for (int o = 128; o > 0; o >>= 1) { if (tid < o) red[tid] += red[tid + o]; __syncthreads(); }
    float inv = rsqrtf(red[0] * (1.f / 1024.f) + 1e-5f);
    float4 gg = *(const float4*)(lng + c);
    float4 bb = *(const float4*)(lnb + c);
    float4 o4;
    o4.x = d0 * inv * gg.x + bb.x;
    o4.y = d1 * inv * gg.y + bb.y;
    o4.z = d2 * inv * gg.z + bb.z;
    o4.w = d3 * inv * gg.w + bb.w;
    size_t off = (size_t)bl * D_ + c;
    *(float4*)(out + off) = o4;
    uint32_t h0, l0, h1, l1;
    split2(o4.x, o4.y, h0, l0);
    split2(o4.z, o4.w, h1, l1);
    *(uint2*)(oh + off) = make_uint2(h0, h1);
    *(uint2*)(ol + off) = make_uint2(l0, l1);
}

// ---------------- residual add + LayerNorm ----------------
__global__ __launch_bounds__(256) void k_add_ln(
    const float* __restrict__ x, const float* __restrict__ zv,
    const float* __restrict__ lng, const float* __restrict__ lnb,
    float* __restrict__ out)
{
    int bl = blockIdx.x;
    int tid = threadIdx.x;
    int c = tid * 4;
    float4 xv = *(const float4*)(x + (size_t)bl * D_ + c);
    float4 zz = *(const float4*)(zv + (size_t)bl * D_ + c);
    float t0 = xv.x + zz.x, t1 = xv.y + zz.y, t2 = xv.z + zz.z, t3 = xv.w + zz.w;

    __shared__ float red[256];
    red[tid] = t0 + t1 + t2 + t3;
    __syncthreads();
    for (int o = 128; o > 0; o >>= 1) { if (tid < o) red[tid] += red[tid + o]; __syncthreads(); }
    float m = red[0] * (1.f / 1024.f);
    __syncthreads();
    float d0 = t0 - m, d1 = t1 - m, d2 = t2 - m, d3 = t3 - m;
    red[tid] = d0 * d0 + d1 * d1 + d2 * d2 + d3 * d3;
    __syncthreads();
    for (int o = 128; o > 0; o >>= 1) { if (tid < o) red[tid] += red[tid + o]; __syncthreads(); }
    float inv = rsqrtf(red[0] * (1.f / 1024.f) + 1e-5f);
    float4 gg = *(const float4*)(lng + c);
    float4 bb = *(const float4*)(lnb + c);
    float4 o4;
    o4.x = d0 * inv * gg.x + bb.x;
    o4.y = d1 * inv * gg.y + bb.y;
    o4.z = d2 * inv * gg.z + bb.z;
    o4.w = d3 * inv * gg.w + bb.w;
    *(float4*)(out + (size_t)bl * D_ + c) = o4;
}

// ---------------- repack kv -> Kp planes, Vt planes ----------------
__global__ __launch_bounds__(256) void k_pack(
    const float* __restrict__ kv, bf16* __restrict__ kph, bf16* __restrict__ kpl,
    bf16* __restrict__ vth, bf16* __restrict__ vtl)
{
    int idx = blockIdx.x * blockDim.x + threadIdx.x;
    int d = idx & 63;
    int h16 = (idx >> 6) & 15;
    int l = (idx >> 10) & (L_ - 1);
    int b = idx >> 21;
    int G = h16 >> 3, h = h16 & 7;
    const float* base = kv + ((size_t)b * L_ + l) * 2048 + h16 * 128 + d;
    float kvk = base[0];
    float kvv = base[64];
    bf16 hh, ll;
    split1(kvk, hh, ll);
    size_t ko = (((size_t)(b * 2 + G) * L_ + l) * 512) + h * 64 + d;
    kph[ko] = hh; kpl[ko] = ll;
    split1(kvv, hh, ll);
    size_t vo = ((size_t)b * 512 + h * 64 + d) * 4096 + G * 2048 + l;
    vth[vo] = hh; vtl[vo] = ll;
}

// ---------------- row softmax: stats + exp + split -> P planes ----------------
__global__ __launch_bounds__(256) void k_rowsoft(
    const float* __restrict__ S, bf16* __restrict__ Ph, bf16* __restrict__ Pl)
{
    const int l = blockIdx.x, G = blockIdx.y, bg = blockIdx.z;
    const size_t roff = ((size_t)bg * L_ + l) * 4096 + (size_t)G * 2048;
    const int tid = threadIdx.x;
    float v[8];
    *(float4*)(v)     = *(const float4*)(S + roff + tid * 8);
    *(float4*)(v + 4) = *(const float4*)(S + roff + tid * 8 + 4);
    float m = v[0];
#pragma unroll
    for (int j = 1; j < 8; j++) m = fmaxf(m, v[j]);
    __shared__ float red[256];
    red[tid] = m;
    __syncthreads();
    for (int o = 128; o > 0; o >>= 1) { if (tid < o) red[tid] = fmaxf(red[tid], red[tid + o]); __syncthreads(); }
    m = red[0];
    __syncthreads();
    float e[8];
    float s = 0.f;
#pragma unroll
    for (int j = 0; j < 8; j++) { e[j] = __expf(v[j] - m); s += e[j]; }
    red[tid] = s;
    __syncthreads();
    for (int o = 128; o > 0; o >>= 1) { if (tid < o) red[tid] += red[tid + o]; __syncthreads(); }
    float inv = 1.f / red[0];
    uint4 ho, lo4;
    split2(e[0] * inv, e[1] * inv, ho.x, lo4.x);
    split2(e[2] * inv, e[3] * inv, ho.y, lo4.y);
    split2(e[4] * inv, e[5] * inv, ho.z, lo4.z);
    split2(e[6] * inv, e[7] * inv, ho.w, lo4.w);
    *(uint4*)(Ph + roff + tid * 8) = ho;
    *(uint4*)(Pl + roff + tid * 8) = lo4;
}

// ---------------- host ----------------
static void fill1(Batch8& bt)
{
    for (int z = 0; z < 8; z++) {
        bt.offA[z] = bt.offB[z] = bt.offC[z] = 0;
        bt.alpha[z] = 1.f;
    }
}

extern "C" void kernel_launch(void* const* d_in, const int* in_sizes, int n_in,
                              void* d_out, int out_size)
{
    (void)in_sizes; (void)n_in; (void)out_size;
    const int*   tok    = (const int*)  d_in[0];
    const float* ctab   = (const float*)d_in[1];
    const float* projw  = (const float*)d_in[2];
    const float* escale = (const float*)d_in[3];
    const float* dww    = (const float*)d_in[4];
    const float* dwb    = (const float*)d_in[5];
    const float* pww    = (const float*)d_in[6];
    const float* pwb    = (const float*)d_in[7];
    const float* gbias  = (const float*)d_in[8];
    const float* clng   = (const float*)d_in[9];
    const float* clnb   = (const float*)d_in[10];
    const float* qw     = (const float*)d_in[11];
    const float* kvw    = (const float*)d_in[12];
    const float* ow     = (const float*)d_in[13];
    const float* alng   = (const float*)d_in[14];
    const float* alnb   = (const float*)d_in[15];

    cudaFuncSetAttribute(gemm_pp, cudaFuncAttributeMaxDynamicSharedMemorySize, GEMM_SMEM);

    float *x, *t2, *q, *S;
    cudaGetSymbolAddress((void**)&x,  g_x);
    cudaGetSymbolAddress((void**)&t2, g_t2);
    cudaGetSymbolAddress((void**)&q,  g_q);
    cudaGetSymbolAddress((void**)&S,  g_s);
    bf16 *t1h, *t1l, *xh, *xl, *qh, *ql, *kph, *kpl, *vth, *vtl, *Ph, *Pl, *Wh, *Wl;
    cudaGetSymbolAddress((void**)&t1h, p_t1h); cudaGetSymbolAddress((void**)&t1l, p_t1l);
    cudaGetSymbolAddress((void**)&xh,  p_xh);  cudaGetSymbolAddress((void**)&xl,  p_xl);
    cudaGetSymbolAddress((void**)&qh,  p_qh);  cudaGetSymbolAddress((void**)&ql,  p_ql);
    cudaGetSymbolAddress((void**)&kph, p_kph); cudaGetSymbolAddress((void**)&kpl, p_kpl);
    cudaGetSymbolAddress((void**)&vth, p_vth); cudaGetSymbolAddress((void**)&vtl, p_vtl);
    cudaGetSymbolAddress((void**)&Ph,  p_Ph);  cudaGetSymbolAddress((void**)&Pl,  p_Pl);
    cudaGetSymbolAddress((void**)&Wh,  p_Wh);  cudaGetSymbolAddress((void**)&Wl,  p_Wl);

    // weight plane offsets: pw@0(4M), qw@4M(2M), kvw@6M(4M), ow@10M(2M)
    const long long OPW = 0, OQW = 4194304, OKV = 6291456, OOW = 10485760;
    k_split4<<<4096, 256>>>(pww, Wh + OPW, Wl + OPW, 1048576);
    k_split4<<<2048, 256>>>(qw,  Wh + OQW, Wl + OQW, 524288);
    k_split4<<<4096, 256>>>(kvw, Wh + OKV, Wl + OKV, 1048576);
    k_split4<<<2048, 256>>>(ow,  Wh + OOW, Wl + OOW, 524288);

    k_embed<<<B_ * L_, 256>>>(tok, ctab, projw, escale, x);

    for (int i = 0; i < 2; i++) {
        // --- conv block ---
        k_dwconv<<<(B_ * L_ * D_) / 256, 256>>>(x, dww + (size_t)i * D_ * 5, dwb + i * D_,
                                                t1h, t1l);

        Batch8 b1; fill1(b1);
        // pointwise: t2(4096x2048) = t1(4096x1024) * pw_w(2048x1024)^T + pw_b
        gemm_pp<<<dim3(8, 32, 1), 512, GEMM_SMEM>>>(
            t1h, t1l, Wh + OPW + (long long)i * 2097152, Wl + OPW + (long long)i * 2097152,
            t2, nullptr, nullptr, pwb + i * 2048, 1024, 1024, 1024, 2048, b1);

        k_glu_ln<<<B_ * L_, 256>>>(x, t2, gbias + i * D_, clng + i * D_, clnb + i * D_,
                                   x, xh, xl);

        // --- attention block ---
        // q (planes out)
        gemm_pp<<<dim3(4, 32, 1), 512, GEMM_SMEM>>>(
            xh, xl, Wh + OQW + (long long)i * 1048576, Wl + OQW + (long long)i * 1048576,
            nullptr, qh, ql, nullptr, 1024, 1024, 1024, 1024, b1);
        // kv (fp32 out)
        gemm_pp<<<dim3(8, 32, 1), 512, GEMM_SMEM>>>(
            xh, xl, Wh + OKV + (long long)i * 2097152, Wl + OKV + (long long)i * 2097152,
            t2, nullptr, nullptr, nullptr, 1024, 1024, 1024, 2048, b1);

        k_pack<<<(B_ * L_ * 16 * 64) / 256, 256>>>(t2, kph, kpl, vth, vtl);

        // scores: per (b,g,G): S = Q_bg(2048x512) * Kp_bG(2048x512)^T * SCALE * fs[G]
        Batch8 bs; fill1(bs);
        for (int zz = 0; zz < 8; zz++) {
            int bg = zz >> 1, G = zz & 1;
            int b = bg >> 1, g = bg & 1;
            bs.offA[zz] = (long long)b * L_ * 1024 + g * 512;
            bs.offB[zz] = (long long)(b * 2 + G) * L_ * 512;
            bs.offC[zz] = (long long)bg * L_ * 4096 + G * 2048;
            bs.alpha[zz] = 0.125f * (G ? 2.0f : 1.0f);
        }
        gemm_pp<<<dim3(8, 16, 8), 512, GEMM_SMEM>>>(
            qh, ql, kph, kpl, S, nullptr, nullptr, nullptr, 512, 1024, 512, 4096, bs);

        k_rowsoft<<<dim3(L_, 2, 4), 256>>>(S, Ph, Pl);

        // attention out: O(2048x512) = P(2048x4096) * Vt(512x4096)^T -> t1 planes
        Batch8 bo; fill1(bo);
        for (int zz = 0; zz < 4; zz++) {
            int b = zz >> 1, g = zz & 1;
            bo.offA[zz] = (long long)zz * L_ * 4096;
            bo.offB[zz] = (long long)b * 512 * 4096;
            bo.offC[zz] = (long long)b * L_ * 1024 + g * 512;
        }
        gemm_pp<<<dim3(2, 16, 4), 512, GEMM_SMEM>>>(
            Ph, Pl, vth, vtl, nullptr, t1h, t1l, nullptr, 4096, 4096, 4096, 1024, bo);

        // out projection (fp32 into q buffer)
        gemm_pp<<<dim3(4, 32, 1), 512, GEMM_SMEM>>>(
            t1h, t1l, Wh + OOW + (long long)i * 1048576, Wl + OOW + (long long)i * 1048576,
            q, nullptr, nullptr, nullptr, 1024, 1024, 1024, 1024, b1);

        float* dst = (i == 1) ? (float*)d_out : x;
        k_add_ln<<<B_ * L_, 256>>>(x, q, alng + i * D_, alnb + i * D_, dst);
    }
}

// round 6
// speedup vs baseline: 3.0816x; 1.1260x over previous
#include <cuda_runtime.h>
#include <cuda_bf16.h>
#include <math.h>
#include <stdint.h>

#define D_ 1024
#define L_ 2048
#define B_ 2

typedef __nv_bfloat16 bf16;

// GEMM: CTA 128x256, 512 thr, warps 4M x 4N (32x64 each), KC=64, 2-stage cp.async
#define STG_BYTES 98304
#define GEMM_SMEM (2 * STG_BYTES + 1024)

// ---------------- fp32 scratch ----------------
__device__ float g_x [B_ * L_ * D_];
__device__ float g_t2[B_ * L_ * 2 * D_];
__device__ float g_q [B_ * L_ * D_];
__device__ float g_s [4LL * L_ * 4096];

// ---------------- bf16 hi/lo planes ----------------
__device__ __align__(16) bf16 p_t1h[B_ * L_ * D_],       p_t1l[B_ * L_ * D_];
__device__ __align__(16) bf16 p_xh [B_ * L_ * D_],       p_xl [B_ * L_ * D_];
__device__ __align__(16) bf16 p_qh [B_ * L_ * D_],       p_ql [B_ * L_ * D_];
__device__ __align__(16) bf16 p_kph[B_ * 2 * L_ * 512],  p_kpl[B_ * 2 * L_ * 512];
__device__ __align__(16) bf16 p_vth[B_ * 512 * 2 * L_],  p_vtl[B_ * 512 * 2 * L_];
__device__ __align__(16) bf16 p_Ph [4LL * L_ * 4096],    p_Pl [4LL * L_ * 4096];
__device__ __align__(16) bf16 p_Wh [12 * 1024 * 1024],   p_Wl [12 * 1024 * 1024];

struct Batch8 {
    long long offA[8];
    long long offB[8];
    long long offC[8];
    float alpha[8];
};

// ---------------- helpers ----------------
__device__ __forceinline__ uint32_t smem_u32(const void* p) {
    uint32_t a;
    asm("{ .reg .u64 t; cvta.to.shared.u64 t, %1; cvt.u32.u64 %0, t; }" : "=r"(a) : "l"(p));
    return a;
}
__device__ __forceinline__ void split2(float a, float b, uint32_t& hi, uint32_t& lo) {
    uint32_t h;
    asm("cvt.rn.satfinite.bf16x2.f32 %0, %1, %2;" : "=r"(h) : "f"(b), "f"(a));
    float ra = a - __uint_as_float(h << 16);
    float rb = b - __uint_as_float(h & 0xffff0000u);
    uint32_t l;
    asm("cvt.rn.satfinite.bf16x2.f32 %0, %1, %2;" : "=r"(l) : "f"(rb), "f"(ra));
    hi = h; lo = l;
}
__device__ __forceinline__ void split1(float a, bf16& h, bf16& l) {
    h = __float2bfloat16_rn(a);
    l = __float2bfloat16_rn(a - __bfloat162float(h));
}
__device__ __forceinline__ void mma_bf16(float* c, const uint32_t* a, uint32_t b0, uint32_t b1) {
    asm volatile(
        "mma.sync.aligned.m16n8k16.row.col.f32.bf16.bf16.f32 "
        "{%0,%1,%2,%3}, {%4,%5,%6,%7}, {%8,%9}, {%0,%1,%2,%3};"
        : "+f"(c[0]), "+f"(c[1]), "+f"(c[2]), "+f"(c[3])
        : "r"(a[0]), "r"(a[1]), "r"(a[2]), "r"(a[3]), "r"(b0), "r"(b1));
}
__device__ __forceinline__ void cpa16(uint32_t s, const bf16* g) {
    asm volatile("cp.async.cg.shared.global [%0], [%1], 16;"
                 :: "r"(s), "l"(__cvta_generic_to_global((const void*)g)) : "memory");
}
__device__ __forceinline__ void ldm4(uint32_t addr, uint32_t* r) {
    asm volatile("ldmatrix.sync.aligned.m8n8.x4.shared.b16 {%0,%1,%2,%3}, [%4];"
                 : "=r"(r[0]), "=r"(r[1]), "=r"(r[2]), "=r"(r[3]) : "r"(addr));
}

// ---------------- plane-operand GEMM: C = alpha * A(MxK) * B(NxK)^T ----------------
// A = Ah + Al, B = Bh + Bl (bf16 hi/lo planes). 3-product split accumulation.
// SMEM stage layout: A 128 rows x 256B [hi 128B | lo 128B], B 256 rows x 256B.
__global__ __launch_bounds__(512, 1) void gemm_pp(
    const bf16* __restrict__ Ah, const bf16* __restrict__ Al,
    const bf16* __restrict__ Bh, const bf16* __restrict__ Bl,
    float* __restrict__ C, bf16* __restrict__ Ch, bf16* __restrict__ Cl,
    const float* __restrict__ bias,
    int K, int lda, int ldb, int ldc, Batch8 bt)
{
    extern __shared__ char dsm[];
    uint32_t base = smem_u32(dsm);
    base = (base + 1023u) & ~1023u;

    const int z = blockIdx.z;
    const bf16* gAh = Ah + bt.offA[z];
    const bf16* gAl = Al + bt.offA[z];
    const bf16* gBh = Bh + bt.offB[z];
    const bf16* gBl = Bl + bt.offB[z];
    const float alpha = bt.alpha[z];

    const int tid = threadIdx.x;
    const int lane = tid & 31;
    const int wid = tid >> 5;
    const int wm = wid >> 2, wn = wid & 3;
    const int bm = blockIdx.y * 128, bn = blockIdx.x * 256;

    // cp.async: per thread 4 A chunks (rows rowT+{0,32,64,96}) + 8 B chunks (+{0..224})
    const int rowT = tid >> 4;            // 0..31
    const int sub  = tid & 15;
    const int plane = sub >> 3;           // 0 = hi, 1 = lo
    const int c4 = sub & 7;               // 16B chunk within 128B plane-row
    const bf16* aP = (plane ? gAl : gAh) + (size_t)(bm + rowT) * lda + c4 * 8;
    const bf16* bP = (plane ? gBl : gBh) + (size_t)(bn + rowT) * ldb + c4 * 8;
    const uint32_t swz = ((uint32_t)c4 * 16u) ^ (((uint32_t)rowT & 7u) << 4);
    const uint32_t sA = base + (uint32_t)rowT * 256u + (uint32_t)plane * 128u + swz;
    const uint32_t sB = base + 32768u + (uint32_t)rowT * 256u + (uint32_t)plane * 128u + swz;
    const size_t stepA = (size_t)32 * lda;
    const size_t stepB = (size_t)32 * ldb;

    // fragment addresses
    const int rA = lane & 15, khA = lane >> 4;
    const uint32_t abase = base + (uint32_t)(wm * 32 + rA) * 256u;
    const uint32_t swA = ((uint32_t)rA & 7u) << 4;
    const int rBr = (lane & 7) + ((lane >> 4) << 3);
    const int khB = (lane >> 3) & 1;
    const uint32_t bbase = base + 32768u + (uint32_t)(wn * 64 + rBr) * 256u;
    const uint32_t swB = ((uint32_t)rBr & 7u) << 4;
    uint32_t acf[4], bcf[4];
#pragma unroll
    for (int s = 0; s < 4; s++) {
        acf[s] = ((uint32_t)((s * 2 + khA) * 16)) ^ swA;
        bcf[s] = ((uint32_t)((s * 2 + khB) * 16)) ^ swB;
    }

    float acc[2][8][4];
#pragma unroll
    for (int i = 0; i < 2; i++)
#pragma unroll
        for (int j = 0; j < 8; j++)
#pragma unroll
            for (int c = 0; c < 4; c++) acc[i][j][c] = 0.f;

    const int nk = K >> 6;

    // prologue: stage 0
#pragma unroll
    for (int i = 0; i < 4; i++) cpa16(sA + i * 8192u, aP + (size_t)i * stepA);
#pragma unroll
    for (int i = 0; i < 8; i++) cpa16(sB + i * 8192u, bP + (size_t)i * stepB);
    asm volatile("cp.async.commit_group;" ::: "memory");

    for (int kt = 0; kt < nk; kt++) {
        if (kt + 1 < nk) {
            const uint32_t so = ((kt + 1) & 1) * (uint32_t)STG_BYTES;
            const int k0 = (kt + 1) << 6;
#pragma unroll
            for (int i = 0; i < 4; i++) cpa16(sA + so + i * 8192u, aP + k0 + (size_t)i * stepA);
#pragma unroll
            for (int i = 0; i < 8; i++) cpa16(sB + so + i * 8192u, bP + k0 + (size_t)i * stepB);
            asm volatile("cp.async.commit_group;" ::: "memory");
            asm volatile("cp.async.wait_group 1;" ::: "memory");
        } else {
            asm volatile("cp.async.wait_group 0;" ::: "memory");
        }
        __syncthreads();
        const uint32_t so = (kt & 1) * (uint32_t)STG_BYTES;
#pragma unroll
        for (int s = 0; s < 4; s++) {
            uint32_t ah[2][4], al[2][4];
#pragma unroll
            for (int mb = 0; mb < 2; mb++) {
                ldm4(abase + so + mb * 4096 + acf[s], ah[mb]);
                ldm4(abase + so + mb * 4096 + 128 + acf[s], al[mb]);
            }
#pragma unroll
            for (int half = 0; half < 2; half++) {
                uint32_t bh[2][4], bl[2][4];
#pragma unroll
                for (int p2 = 0; p2 < 2; p2++) {
                    const int pr = half * 2 + p2;
                    ldm4(bbase + so + pr * 4096 + bcf[s], bh[p2]);
                    ldm4(bbase + so + pr * 4096 + 128 + bcf[s], bl[p2]);
                }
                // product 1: Ah x Bh (8 MMAs, distinct accumulators)
#pragma unroll
                for (int p2 = 0; p2 < 2; p2++)
#pragma unroll
                    for (int nb2 = 0; nb2 < 2; nb2++)
#pragma unroll
                        for (int mb = 0; mb < 2; mb++)
                            mma_bf16(acc[mb][(half * 2 + p2) * 2 + nb2],
                                     ah[mb], bh[p2][nb2 * 2], bh[p2][nb2 * 2 + 1]);
                // product 2: Ah x Bl
#pragma unroll
                for (int p2 = 0; p2 < 2; p2++)
#pragma unroll
                    for (int nb2 = 0; nb2 < 2; nb2++)
#pragma unroll
                        for (int mb = 0; mb < 2; mb++)
                            mma_bf16(acc[mb][(half * 2 + p2) * 2 + nb2],
                                     ah[mb], bl[p2][nb2 * 2], bl[p2][nb2 * 2 + 1]);
                // product 3: Al x Bh
#pragma unroll
                for (int p2 = 0; p2 < 2; p2++)
#pragma unroll
                    for (int nb2 = 0; nb2 < 2; nb2++)
#pragma unroll
                        for (int mb = 0; mb < 2; mb++)
                            mma_bf16(acc[mb][(half * 2 + p2) * 2 + nb2],
                                     al[mb], bh[p2][nb2 * 2], bh[p2][nb2 * 2 + 1]);
            }
        }
        __syncthreads();
    }

    // ---- epilogue ----
    const int qr = lane >> 2, qc = lane & 3;
    if (Ch) {
#pragma unroll
        for (int mb = 0; mb < 2; mb++) {
            const int row = bm + wm * 32 + mb * 16 + qr;
#pragma unroll
            for (int nb = 0; nb < 8; nb++) {
                const int col = bn + wn * 64 + nb * 8 + qc * 2;
                uint32_t h0, l0, h1, l1;
                split2(acc[mb][nb][0] * alpha, acc[mb][nb][1] * alpha, h0, l0);
                split2(acc[mb][nb][2] * alpha, acc[mb][nb][3] * alpha, h1, l1);
                const long long o0 = bt.offC[z] + (long long)row * ldc + col;
                const long long o1 = bt.offC[z] + (long long)(row + 8) * ldc + col;
                *(uint32_t*)(Ch + o0) = h0; *(uint32_t*)(Cl + o0) = l0;
                *(uint32_t*)(Ch + o1) = h1; *(uint32_t*)(Cl + o1) = l1;
            }
        }
    } else {
        float* Cz = C + bt.offC[z];
#pragma unroll
        for (int mb = 0; mb < 2; mb++) {
            const int row = bm + wm * 32 + mb * 16 + qr;
#pragma unroll
            for (int nb = 0; nb < 8; nb++) {
                const int col = bn + wn * 64 + nb * 8 + qc * 2;
                float2 v0, v1;
                v0.x = acc[mb][nb][0] * alpha;
                v0.y = acc[mb][nb][1] * alpha;
                v1.x = acc[mb][nb][2] * alpha;
                v1.y = acc[mb][nb][3] * alpha;
                if (bias) {
                    float2 bv = *(const float2*)(bias + col);
                    v0.x += bv.x; v0.y += bv.y;
                    v1.x += bv.x; v1.y += bv.y;
                }
                *(float2*)(Cz + (size_t)row * ldc + col) = v0;
                *(float2*)(Cz + (size_t)(row + 8) * ldc + col) = v1;
            }
        }
    }
}

// ---------------- weight split: fp32 -> hi/lo planes ----------------
__global__ __launch_bounds__(256) void k_split4(
    const float* __restrict__ w, bf16* __restrict__ h, bf16* __restrict__ l, int n4)
{
    int i = blockIdx.x * 256 + threadIdx.x;
    if (i < n4) {
        float4 v = ((const float4*)w)[i];
        uint32_t h0, l0, h1, l1;
        split2(v.x, v.y, h0, l0);
        split2(v.z, v.w, h1, l1);
        ((uint2*)h)[i] = make_uint2(h0, h1);
        ((uint2*)l)[i] = make_uint2(l0, l1);
    }
}

// ---------------- Julia embedding ----------------
__global__ __launch_bounds__(256) void k_embed(
    const int* __restrict__ tok, const float* __restrict__ ctab,
    const float* __restrict__ projw, const float* __restrict__ escale,
    float* __restrict__ x)
{
    int bl = blockIdx.x;
    int t = tok[bl];
    float cr = ctab[2 * t], ci = ctab[2 * t + 1];
    float f[16];
    float zr = 0.f, zi = 0.f;
#pragma unroll
    for (int s = 0; s < 8; s++) {
        float nr = zr * zr - zi * zi + cr;
        float ni = 2.f * zr * zi + ci;
        zr = nr; zi = ni;
        f[2 * s] = zr; f[2 * s + 1] = zi;
    }
    float es = escale[0];
    int d0 = threadIdx.x * 4;
    float4 o;
    float* op = &o.x;
#pragma unroll
    for (int j = 0; j < 4; j++) {
        const float* w = projw + (size_t)(d0 + j) * 16;
        float acc = 0.f;
#pragma unroll
        for (int k = 0; k < 16; k++) acc = fmaf(f[k], w[k], acc);
        op[j] = acc * es;
    }
    *(float4*)(x + (size_t)bl * D_ + d0) = o;
}

// ---------------- depthwise conv (K=5) -> planes ----------------
__global__ __launch_bounds__(256) void k_dwconv(
    const float* __restrict__ x, const float* __restrict__ w,
    const float* __restrict__ bias, bf16* __restrict__ yh, bf16* __restrict__ yl)
{
    int idx = blockIdx.x * blockDim.x + threadIdx.x;
    int d = idx & (D_ - 1);
    int l = (idx >> 10) & (L_ - 1);
    int b = idx >> 21;
    float acc = bias[d];
#pragma unroll
    for (int k = 0; k < 5; k++) {
        int ll = l + k - 2;
        if (ll >= 0 && ll < L_)
            acc = fmaf(x[((size_t)b * L_ + ll) * D_ + d], w[d * 5 + k], acc);
    }
    bf16 h, lo;
    split1(acc, h, lo);
    yh[idx] = h; yl[idx] = lo;
}

// ---------------- GLU + residual + LayerNorm -> fp32 x + planes ----------------
__global__ __launch_bounds__(256) void k_glu_ln(
    const float* __restrict__ x, const float* __restrict__ y2,
    const float* __restrict__ gbias, const float* __restrict__ lng,
    const float* __restrict__ lnb, float* __restrict__ out,
    bf16* __restrict__ oh, bf16* __restrict__ ol)
{
    int bl = blockIdx.x;
    int tid = threadIdx.x;
    int c = tid * 4;
    const float* xr = x + (size_t)bl * D_;
    const float* yr = y2 + (size_t)bl * 2 * D_;
    float4 xv = *(const float4*)(xr + c);
    float4 sv = *(const float4*)(yr + c);
    float4 gv = *(const float4*)(yr + D_ + c);
    float4 gb = *(const float4*)(gbias + c);
    float t0 = xv.x + sv.x * (1.f / (1.f + __expf(-(gv.x + gb.x))));
    float t1 = xv.y + sv.y * (1.f / (1.f + __expf(-(gv.y + gb.y))));
    float t2 = xv.z + sv.z * (1.f / (1.f + __expf(-(gv.z + gb.z))));
    float t3 = xv.w + sv.w * (1.f / (1.f + __expf(-(gv.w + gb.w))));

    __shared__ float red[256];
    red[tid] = t0 + t1 + t2 + t3;
    __syncthreads();
    for (int o = 128; o > 0; o >>= 1) { if (tid < o) red[tid] += red[tid + o]; __syncthreads(); }
    float m = red[0] * (1.f / 1024.f);
    __syncthreads();
    float d0 = t0 - m, d1 = t1 - m, d2 = t2 - m, d3 = t3 - m;
    red[tid] = d0 * d0 + d1 * d1 + d2 * d2 + d3 * d3;
    __syncthreads();
    for (int o = 128; o > 0; o >>= 1) { if (tid < o) red[tid] += red[tid + o]; __syncthreads(); }
    float inv = rsqrtf(red[0] * (1.f / 1024.f) + 1e-5f);
    float4 gg = *(const float4*)(lng + c);
    float4 bb = *(const float4*)(lnb + c);
    float4 o4;
    o4.x = d0 * inv * gg.x + bb.x;
    o4.y = d1 * inv * gg.y + bb.y;
    o4.z = d2 * inv * gg.z + bb.z;
    o4.w = d3 * inv * gg.w + bb.w;
    size_t off = (size_t)bl * D_ + c;
    *(float4*)(out + off) = o4;
    uint32_t h0, l0, h1, l1;
    split2(o4.x, o4.y, h0, l0);
    split2(o4.z, o4.w, h1, l1);
    *(uint2*)(oh + off) = make_uint2(h0, h1);
    *(uint2*)(ol + off) = make_uint2(l0, l1);
}

// ---------------- residual add + LayerNorm ----------------
__global__ __launch_bounds__(256) void k_add_ln(
    const float* __restrict__ x, const float* __restrict__ zv,
    const float* __restrict__ lng, const float* __restrict__ lnb,
    float* __restrict__ out)
{
    int bl = blockIdx.x;
    int tid = threadIdx.x;
    int c = tid * 4;
    float4 xv = *(const float4*)(x + (size_t)bl * D_ + c);
    float4 zz = *(const float4*)(zv + (size_t)bl * D_ + c);
    float t0 = xv.x + zz.x, t1 = xv.y + zz.y, t2 = xv.z + zz.z, t3 = xv.w + zz.w;

    __shared__ float red[256];
    red[tid] = t0 + t1 + t2 + t3;
    __syncthreads();
    for (int o = 128; o > 0; o >>= 1) { if (tid < o) red[tid] += red[tid + o]; __syncthreads(); }
    float m = red[0] * (1.f / 1024.f);
    __syncthreads();
    float d0 = t0 - m, d1 = t1 - m, d2 = t2 - m, d3 = t3 - m;
    red[tid] = d0 * d0 + d1 * d1 + d2 * d2 + d3 * d3;
    __syncthreads();
    for (int o = 128; o > 0; o >>= 1) { if (tid < o) red[tid] += red[tid + o]; __syncthreads(); }
    float inv = rsqrtf(red[0] * (1.f / 1024.f) + 1e-5f);
    float4 gg = *(const float4*)(lng + c);
    float4 bb = *(const float4*)(lnb + c);
    float4 o4;
    o4.x = d0 * inv * gg.x + bb.x;
    o4.y = d1 * inv * gg.y + bb.y;
    o4.z = d2 * inv * gg.z + bb.z;
    o4.w = d3 * inv * gg.w + bb.w;
    *(float4*)(out + (size_t)bl * D_ + c) = o4;
}

// ---------------- K pack (coalesced both sides) ----------------
__global__ __launch_bounds__(256) void k_packk(
    const float* __restrict__ kv, bf16* __restrict__ kph, bf16* __restrict__ kpl)
{
    int idx = blockIdx.x * blockDim.x + threadIdx.x;
    int d = idx & 63;
    int h16 = (idx >> 6) & 15;
    int l = (idx >> 10) & (L_ - 1);
    int b = idx >> 21;
    int G = h16 >> 3, h = h16 & 7;
    float kvk = kv[((size_t)b * L_ + l) * 2048 + h16 * 128 + d];
    bf16 hh, ll;
    split1(kvk, hh, ll);
    size_t ko = (((size_t)(b * 2 + G) * L_ + l) * 512) + h * 64 + d;
    kph[ko] = hh; kpl[ko] = ll;
}

// ---------------- V transpose via smem tile (coalesced both sides) ----------------
__global__ __launch_bounds__(256) void k_packv(
    const float* __restrict__ kv, bf16* __restrict__ vth, bf16* __restrict__ vtl)
{
    __shared__ float tile[64][65];
    const int lt = blockIdx.x;      // 0..31
    const int h16 = blockIdx.y;     // 0..15
    const int b = blockIdx.z;       // 0..1
    const int l0 = lt * 64;
    const int tid = threadIdx.x;
    const int dcol = tid & 63;
    const int r4 = tid >> 6;        // 0..3
#pragma unroll
    for (int i = 0; i < 16; i++) {
        int row = i * 4 + r4;
        tile[row][dcol] = kv[((size_t)b * L_ + l0 + row) * 2048 + h16 * 128 + 64 + dcol];
    }
    __syncthreads();
    const int G = h16 >> 3, h = h16 & 7;
#pragma unroll
    for (int i = 0; i < 16; i++) {
        int dim = i * 4 + r4;
        float v = tile[dcol][dim];
        bf16 hh, ll;
        split1(v, hh, ll);
        size_t o = ((size_t)b * 512 + h * 64 + dim) * 4096 + (size_t)G * 2048 + l0 + dcol;
        vth[o] = hh; vtl[o] = ll;
    }
}

// ---------------- row softmax: stats + exp + split -> P planes ----------------
__global__ __launch_bounds__(256) void k_rowsoft(
    const float* __restrict__ S, bf16* __restrict__ Ph, bf16* __restrict__ Pl)
{
    const int l = blockIdx.x, G = blockIdx.y, bg = blockIdx.z;
    const size_t roff = ((size_t)bg * L_ + l) * 4096 + (size_t)G * 2048;
    const int tid = threadIdx.x;
    float v[8];
    *(float4*)(v)     = *(const float4*)(S + roff + tid * 8);
    *(float4*)(v + 4) = *(const float4*)(S + roff + tid * 8 + 4);
    float m = v[0];
#pragma unroll
    for (int j = 1; j < 8; j++) m = fmaxf(m, v[j]);
    __shared__ float red[256];
    red[tid] = m;
    __syncthreads();
    for (int o = 128; o > 0; o >>= 1) { if (tid < o) red[tid] = fmaxf(red[tid], red[tid + o]); __syncthreads(); }
    m = red[0];
    __syncthreads();
    float e[8];
    float s = 0.f;
#pragma unroll
    for (int j = 0; j < 8; j++) { e[j] = __expf(v[j] - m); s += e[j]; }
    red[tid] = s;
    __syncthreads();
    for (int o = 128; o > 0; o >>= 1) { if (tid < o) red[tid] += red[tid + o]; __syncthreads(); }
    float inv = 1.f / red[0];
    uint4 ho, lo4;
    split2(e[0] * inv, e[1] * inv, ho.x, lo4.x);
    split2(e[2] * inv, e[3] * inv, ho.y, lo4.y);
    split2(e[4] * inv, e[5] * inv, ho.z, lo4.z);
    split2(e[6] * inv, e[7] * inv, ho.w, lo4.w);
    *(uint4*)(Ph + roff + tid * 8) = ho;
    *(uint4*)(Pl + roff + tid * 8) = lo4;
}

// ---------------- host ----------------
static void fill1(Batch8& bt)
{
    for (int z = 0; z < 8; z++) {
        bt.offA[z] = bt.offB[z] = bt.offC[z] = 0;
        bt.alpha[z] = 1.f;
    }
}

extern "C" void kernel_launch(void* const* d_in, const int* in_sizes, int n_in,
                              void* d_out, int out_size)
{
    (void)in_sizes; (void)n_in; (void)out_size;
    const int*   tok    = (const int*)  d_in[0];
    const float* ctab   = (const float*)d_in[1];
    const float* projw  = (const float*)d_in[2];
    const float* escale = (const float*)d_in[3];
    const float* dww    = (const float*)d_in[4];
    const float* dwb    = (const float*)d_in[5];
    const float* pww    = (const float*)d_in[6];
    const float* pwb    = (const float*)d_in[7];
    const float* gbias  = (const float*)d_in[8];
    const float* clng   = (const float*)d_in[9];
    const float* clnb   = (const float*)d_in[10];
    const float* qw     = (const float*)d_in[11];
    const float* kvw    = (const float*)d_in[12];
    const float* ow     = (const float*)d_in[13];
    const float* alng   = (const float*)d_in[14];
    const float* alnb   = (const float*)d_in[15];

    cudaFuncSetAttribute(gemm_pp, cudaFuncAttributeMaxDynamicSharedMemorySize, GEMM_SMEM);

    float *x, *t2, *q, *S;
    cudaGetSymbolAddress((void**)&x,  g_x);
    cudaGetSymbolAddress((void**)&t2, g_t2);
    cudaGetSymbolAddress((void**)&q,  g_q);
    cudaGetSymbolAddress((void**)&S,  g_s);
    bf16 *t1h, *t1l, *xh, *xl, *qh, *ql, *kph, *kpl, *vth, *vtl, *Ph, *Pl, *Wh, *Wl;
    cudaGetSymbolAddress((void**)&t1h, p_t1h); cudaGetSymbolAddress((void**)&t1l, p_t1l);
    cudaGetSymbolAddress((void**)&xh,  p_xh);  cudaGetSymbolAddress((void**)&xl,  p_xl);
    cudaGetSymbolAddress((void**)&qh,  p_qh);  cudaGetSymbolAddress((void**)&ql,  p_ql);
    cudaGetSymbolAddress((void**)&kph, p_kph); cudaGetSymbolAddress((void**)&kpl, p_kpl);
    cudaGetSymbolAddress((void**)&vth, p_vth); cudaGetSymbolAddress((void**)&vtl, p_vtl);
    cudaGetSymbolAddress((void**)&Ph,  p_Ph);  cudaGetSymbolAddress((void**)&Pl,  p_Pl);
    cudaGetSymbolAddress((void**)&Wh,  p_Wh);  cudaGetSymbolAddress((void**)&Wl,  p_Wl);

    // weight plane offsets: pw@0(4M), qw@4M(2M), kvw@6M(4M), ow@10M(2M)
    const long long OPW = 0, OQW = 4194304, OKV = 6291456, OOW = 10485760;
    k_split4<<<4096, 256>>>(pww, Wh + OPW, Wl + OPW, 1048576);
    k_split4<<<2048, 256>>>(qw,  Wh + OQW, Wl + OQW, 524288);
    k_split4<<<4096, 256>>>(kvw, Wh + OKV, Wl + OKV, 1048576);
    k_split4<<<2048, 256>>>(ow,  Wh + OOW, Wl + OOW, 524288);

    k_embed<<<B_ * L_, 256>>>(tok, ctab, projw, escale, x);

    for (int i = 0; i < 2; i++) {
        // --- conv block ---
        k_dwconv<<<(B_ * L_ * D_) / 256, 256>>>(x, dww + (size_t)i * D_ * 5, dwb + i * D_,
                                                t1h, t1l);

        Batch8 b1; fill1(b1);
        // pointwise: t2(4096x2048) = t1(4096x1024) * pw_w(2048x1024)^T + pw_b
        gemm_pp<<<dim3(8, 32, 1), 512, GEMM_SMEM>>>(
            t1h, t1l, Wh + OPW + (long long)i * 2097152, Wl + OPW + (long long)i * 2097152,
            t2, nullptr, nullptr, pwb + i * 2048, 1024, 1024, 1024, 2048, b1);

        k_glu_ln<<<B_ * L_, 256>>>(x, t2, gbias + i * D_, clng + i * D_, clnb + i * D_,
                                   x, xh, xl);

        // --- attention block ---
        // q (planes out)
        gemm_pp<<<dim3(4, 32, 1), 512, GEMM_SMEM>>>(
            xh, xl, Wh + OQW + (long long)i * 1048576, Wl + OQW + (long long)i * 1048576,
            nullptr, qh, ql, nullptr, 1024, 1024, 1024, 1024, b1);
        // kv (fp32 out)
        gemm_pp<<<dim3(8, 32, 1), 512, GEMM_SMEM>>>(
            xh, xl, Wh + OKV + (long long)i * 2097152, Wl + OKV + (long long)i * 2097152,
            t2, nullptr, nullptr, nullptr, 1024, 1024, 1024, 2048, b1);

        k_packk<<<(B_ * L_ * 16 * 64) / 256, 256>>>(t2, kph, kpl);
        k_packv<<<dim3(32, 16, 2), 256>>>(t2, vth, vtl);

        // scores: per (b,g,G): S = Q_bg(2048x512) * Kp_bG(2048x512)^T * SCALE * fs[G]
        Batch8 bs; fill1(bs);
        for (int zz = 0; zz < 8; zz++) {
            int bg = zz >> 1, G = zz & 1;
            int b = bg >> 1, g = bg & 1;
            bs.offA[zz] = (long long)b * L_ * 1024 + g * 512;
            bs.offB[zz] = (long long)(b * 2 + G) * L_ * 512;
            bs.offC[zz] = (long long)bg * L_ * 4096 + G * 2048;
            bs.alpha[zz] = 0.125f * (G ? 2.0f : 1.0f);
        }
        gemm_pp<<<dim3(8, 16, 8), 512, GEMM_SMEM>>>(
            qh, ql, kph, kpl, S, nullptr, nullptr, nullptr, 512, 1024, 512, 4096, bs);

        k_rowsoft<<<dim3(L_, 2, 4), 256>>>(S, Ph, Pl);

        // attention out: O(2048x512) = P(2048x4096) * Vt(512x4096)^T -> t1 planes
        Batch8 bo; fill1(bo);
        for (int zz = 0; zz < 4; zz++) {
            int b = zz >> 1, g = zz & 1;
            bo.offA[zz] = (long long)zz * L_ * 4096;
            bo.offB[zz] = (long long)b * 512 * 4096;
            bo.offC[zz] = (long long)b * L_ * 1024 + g * 512;
        }
        gemm_pp<<<dim3(2, 16, 4), 512, GEMM_SMEM>>>(
            Ph, Pl, vth, vtl, nullptr, t1h, t1l, nullptr, 4096, 4096, 4096, 1024, bo);

        // out projection (fp32 into q buffer)
        gemm_pp<<<dim3(4, 32, 1), 512, GEMM_SMEM>>>(
            t1h, t1l, Wh + OOW + (long long)i * 1048576, Wl + OOW + (long long)i * 1048576,
            q, nullptr, nullptr, nullptr, 1024, 1024, 1024, 1024, b1);

        float* dst = (i == 1) ? (float*)d_out : x;
        k_add_ln<<<B_ * L_, 256>>>(x, q, alng + i * D_, alnb + i * D_, dst);
    }
}